// round 14
// baseline (speedup 1.0000x reference)
#include <cuda_runtime.h>
#include <cuda_fp16.h>
#include <math.h>

// Problem constants
#define Lx  6
#define Hd  512
#define NHd 8
#define FFd 2048
#define Vocab 10000
#define Bd  4
#define Sd  2048
#define DKd 64
#define Nt  (Bd*Sd)     // 8192 tokens
#define QKVW 1536       // fused QKV width
#define QW2 768         // QKVW/2 words
#define HW2 256         // Hd/2 words
#define FW2 1024        // FFd/2 words

// ---------------- scratch (static device globals; no runtime alloc) ----------------
__device__ float    g_x[Nt*Hd];           // fp32 running activations
__device__ unsigned g_h[Nt*HW2];          // half2-packed LN output
__device__ unsigned g_qkv[Nt*QW2];        // half2-packed fused q|k|v
__device__ unsigned g_ctx[Nt*HW2];        // half2-packed attention output
__device__ unsigned g_ff[Nt*FW2];         // half2-packed FFN hidden
// prepacked fp16 weights: [K/2 words][N], word = half2(W[2k][n], W[2k+1][n])
__device__ unsigned g_wqkv[Lx*HW2*QKVW];
__device__ unsigned g_wo[Lx*HW2*Hd];
__device__ unsigned g_w1[Lx*HW2*FFd];
__device__ unsigned g_w2[Lx*FW2*Hd];
__device__ unsigned g_wg[HW2*Vocab];
__device__ float    g_bqkv[Lx*QKVW];

// ---------------- helpers ----------------
__device__ __forceinline__ unsigned pack2(float a, float b) {
    __half2 h2 = __floats2half2_rn(a, b);   // .x = low = a
    return *reinterpret_cast<unsigned*>(&h2);
}

__device__ __forceinline__ void mma16(float* c,
                                      unsigned a0, unsigned a1, unsigned a2, unsigned a3,
                                      unsigned b0, unsigned b1) {
    asm volatile(
        "mma.sync.aligned.m16n8k16.row.col.f32.f16.f16.f32 "
        "{%0,%1,%2,%3}, {%4,%5,%6,%7}, {%8,%9}, {%0,%1,%2,%3};"
        : "+f"(c[0]), "+f"(c[1]), "+f"(c[2]), "+f"(c[3])
        : "r"(a0), "r"(a1), "r"(a2), "r"(a3), "r"(b0), "r"(b1));
}

__device__ __forceinline__ void cpa16(unsigned dst, const void* src) {
    asm volatile("cp.async.ca.shared.global [%0], [%1], 16;" :: "r"(dst), "l"(src));
}
__device__ __forceinline__ void cpa16p(unsigned dst, const void* src, int bytes) {
    asm volatile("cp.async.ca.shared.global [%0], [%1], 16, %2;" :: "r"(dst), "l"(src), "r"(bytes));
}
__device__ __forceinline__ void cp_commit() { asm volatile("cp.async.commit_group;"); }
template<int N> __device__ __forceinline__ void cp_wait() {
    asm volatile("cp.async.wait_group %0;" :: "n"(N));
}

// ---------------- weight prepack (vectorized): fp32 [rows][N] -> half2 [rows/2][N] ----------------
__global__ void conv_pack(const float* __restrict__ src,
                          unsigned* __restrict__ dst, int N, int totalWords)
{
    int N4 = N >> 2;
    int totalQ = totalWords >> 2;
    for (int q = blockIdx.x * blockDim.x + threadIdx.x;
         q < totalQ; q += gridDim.x * blockDim.x) {
        int r2 = q / N4, n4 = q - r2 * N4;
        const float4 a = *(const float4*)&src[(size_t)(2*r2)*N + n4*4];
        const float4 c = *(const float4*)&src[(size_t)(2*r2+1)*N + n4*4];
        uint4 w;
        w.x = pack2(a.x, c.x);
        w.y = pack2(a.y, c.y);
        w.z = pack2(a.z, c.z);
        w.w = pack2(a.w, c.w);
        *(uint4*)&dst[(size_t)q*4] = w;
    }
}

__global__ void pack_qkv_kernel(const float* __restrict__ Wq,
                                const float* __restrict__ Wk,
                                const float* __restrict__ Wv,
                                unsigned* __restrict__ dst)
{
    const int N4 = QKVW >> 2;
    int totalQ = Lx*HW2*N4;
    for (int q = blockIdx.x * blockDim.x + threadIdx.x;
         q < totalQ; q += gridDim.x * blockDim.x) {
        int l = q / (HW2*N4);
        int rem = q - l * HW2*N4;
        int k2 = rem / N4;
        int n = (rem - k2 * N4) * 4;
        const float* Wm; int nn;
        if (n < Hd)        { Wm = Wq; nn = n; }
        else if (n < 2*Hd) { Wm = Wk; nn = n - Hd; }
        else               { Wm = Wv; nn = n - 2*Hd; }
        const float4 a = *(const float4*)&Wm[(size_t)l*Hd*Hd + (size_t)(2*k2)*Hd + nn];
        const float4 c = *(const float4*)&Wm[(size_t)l*Hd*Hd + (size_t)(2*k2+1)*Hd + nn];
        uint4 w;
        w.x = pack2(a.x, c.x);
        w.y = pack2(a.y, c.y);
        w.z = pack2(a.z, c.z);
        w.w = pack2(a.w, c.w);
        *(uint4*)&dst[((size_t)l*HW2 + k2)*QKVW + n] = w;
    }
}

__global__ void pack_bqkv_kernel(const float* __restrict__ bq,
                                 const float* __restrict__ bk,
                                 const float* __restrict__ bv,
                                 float* __restrict__ dst)
{
    int idx = blockIdx.x * blockDim.x + threadIdx.x;
    if (idx >= Lx*QKVW) return;
    int l = idx / QKVW;
    int n = idx - l * QKVW;
    float val;
    if (n < Hd)        val = bq[l*Hd + n];
    else if (n < 2*Hd) val = bk[l*Hd + (n - Hd)];
    else               val = bv[l*Hd + (n - 2*Hd)];
    dst[idx] = val;
}

// ---------------- embedding + sinusoidal positional encoding ----------------
__global__ void embed_kernel(const int* __restrict__ src,
                             const float* __restrict__ emb,
                             float* __restrict__ x)
{
    int idx = blockIdx.x * blockDim.x + threadIdx.x;
    if (idx >= Nt*Hd) return;
    int n = idx >> 9;
    int c = idx & (Hd-1);
    int s = n & (Sd-1);
    int tok = src[n];
    int i2 = c & ~1;
    float div = expf(-(logf(10000.0f)/(float)Hd) * (float)i2);
    float ang = (float)s * div;
    float pe = (c & 1) ? cosf(ang) : sinf(ang);
    x[idx] = emb[(size_t)tok*Hd + c] + pe;
}

// ---------------- layernorm: warp per row, no block sync. fp32 in -> half2 out ----------------
__global__ void layernorm_kernel(const float* __restrict__ x,
                                 const float* __restrict__ g,
                                 const float* __restrict__ b,
                                 unsigned* __restrict__ out)
{
    int wid = threadIdx.x >> 5, lane = threadIdx.x & 31;
    int row = blockIdx.x * 8 + wid;
    const float* xr = x + (size_t)row*Hd;

    // 4 chunks of 128 cols; lane handles cols chunk*128 + lane*4 .. +3
    float4 v[4];
    #pragma unroll
    for (int ch = 0; ch < 4; ch++)
        v[ch] = *(const float4*)(xr + ch*128 + lane*4);

    float s = 0.f;
    #pragma unroll
    for (int ch = 0; ch < 4; ch++) s += v[ch].x + v[ch].y + v[ch].z + v[ch].w;
    #pragma unroll
    for (int o = 16; o > 0; o >>= 1) s += __shfl_xor_sync(0xffffffffu, s, o);
    float mean = s * (1.0f/(float)Hd);

    float ss = 0.f;
    #pragma unroll
    for (int ch = 0; ch < 4; ch++) {
        float dx = v[ch].x - mean, dy = v[ch].y - mean;
        float dz = v[ch].z - mean, dw = v[ch].w - mean;
        ss += dx*dx + dy*dy + dz*dz + dw*dw;
    }
    #pragma unroll
    for (int o = 16; o > 0; o >>= 1) ss += __shfl_xor_sync(0xffffffffu, ss, o);
    float rstd = rsqrtf(ss * (1.0f/(float)Hd) + 1e-5f);

    #pragma unroll
    for (int ch = 0; ch < 4; ch++) {
        int c = ch*128 + lane*4;
        float4 gg = *(const float4*)(g + c);
        float4 bb = *(const float4*)(b + c);
        float o0 = (v[ch].x - mean)*rstd*gg.x + bb.x;
        float o1 = (v[ch].y - mean)*rstd*gg.y + bb.y;
        float o2 = (v[ch].z - mean)*rstd*gg.z + bb.z;
        float o3 = (v[ch].w - mean)*rstd*gg.w + bb.w;
        uint2 w2 = make_uint2(pack2(o0, o1), pack2(o2, o3));
        *(uint2*)(out + (size_t)row*HW2 + (c >> 1)) = w2;
    }
}

// ============================================================================
// fp16 GEMM: A [M][K2] half2 words (k-pairs), B [K2][N] half2 words.
// 128x128 tile, 32-k (16 words) per stage, 4-stage cp.async (loads issued
// before compute, exact tail-aware wait), m16n8k16.
// OUT modes: 0 = f32 + residual, 2 = half2+relu,
//            3 = half2 with cols<Hd scaled 0.125 (fused QKV), 4 = f32 plain
// ============================================================================
#define GKTW 16     // k-words per stage (32 k)
#define APAD 20
#define BPAD 136
#define NSTG 4
#define GEMM_SMEM ((NSTG*128*APAD + NSTG*GKTW*BPAD) * 4)

template<int OM>
__global__ void __launch_bounds__(256, 2)
gemm_hk(const unsigned* __restrict__ A,
        const unsigned* __restrict__ B,
        const float* __restrict__ bias,
        const float* __restrict__ R,
        void* __restrict__ Cv,
        int M, int N, int K2)
{
    extern __shared__ unsigned gsm[];
    unsigned* As = gsm;                   // [NSTG][128][APAD]
    unsigned* Bs = gsm + NSTG*128*APAD;   // [NSTG][GKTW][BPAD]

    int tid = threadIdx.x;
    int wid = tid >> 5, lane = tid & 31;
    int g = lane >> 2, t = lane & 3;
    int wm = (wid >> 2) * 64;
    int wn = (wid & 3) * 32;
    int rowBase = blockIdx.y * 128;
    int colBase = blockIdx.x * 128;

    float acc[4][4][4];
    #pragma unroll
    for (int mi = 0; mi < 4; mi++)
        #pragma unroll
        for (int ni = 0; ni < 4; ni++)
            #pragma unroll
            for (int r = 0; r < 4; r++) acc[mi][ni][r] = 0.0f;

    int nst = K2 / GKTW;

    auto loadStage = [&](int st, int k0w) {
        unsigned* Adst = As + st*128*APAD;
        unsigned* Bdst = Bs + st*GKTW*BPAD;
        #pragma unroll
        for (int i = 0; i < 2; i++) {
            int li = tid + i * 256;
            int r = li >> 2, kq = (li & 3) * 4;
            cpa16((unsigned)__cvta_generic_to_shared(&Adst[r*APAD + kq]),
                  &A[(size_t)(rowBase + r) * K2 + k0w + kq]);
        }
        #pragma unroll
        for (int i = 0; i < 2; i++) {
            int li = tid + i * 256;
            int r = li >> 5, cq = (li & 31) * 4;
            int gc = colBase + cq;
            cpa16p((unsigned)__cvta_generic_to_shared(&Bdst[r*BPAD + cq]),
                   &B[(size_t)(k0w + r) * N + gc], (gc + 4 <= N) ? 16 : 0);
        }
        cp_commit();
    };

    auto computeStage = [&](int st) {
        const unsigned* Asrc = As + st*128*APAD;
        const unsigned* Bsrc = Bs + st*GKTW*BPAD;
        #pragma unroll
        for (int kk2 = 0; kk2 < GKTW; kk2 += 8) {   // 2 x k16 chunks
            unsigned a[4][4], b[4][2];
            #pragma unroll
            for (int mi = 0; mi < 4; mi++) {
                int m = wm + mi * 16 + g;
                a[mi][0] = Asrc[m*APAD       + kk2 + t];
                a[mi][1] = Asrc[(m + 8)*APAD + kk2 + t];
                a[mi][2] = Asrc[m*APAD       + kk2 + 4 + t];
                a[mi][3] = Asrc[(m + 8)*APAD + kk2 + 4 + t];
            }
            #pragma unroll
            for (int ni = 0; ni < 4; ni++) {
                int n = wn + ni * 8 + g;
                b[ni][0] = Bsrc[(kk2 + t)*BPAD     + n];
                b[ni][1] = Bsrc[(kk2 + 4 + t)*BPAD + n];
            }
            #pragma unroll
            for (int mi = 0; mi < 4; mi++)
                #pragma unroll
                for (int ni = 0; ni < 4; ni++)
                    mma16(acc[mi][ni], a[mi][0], a[mi][1], a[mi][2], a[mi][3],
                          b[ni][0], b[ni][1]);
        }
    };

    int issued = (nst < 3) ? nst : 3;
    for (int p = 0; p < issued; p++) loadStage(p, p * GKTW);

    for (int s = 0; s < nst; s++) {
        int allow = issued - s - 1;       // groups allowed outstanding
        if (allow >= 2)      cp_wait<2>();
        else if (allow == 1) cp_wait<1>();
        else                 cp_wait<0>();
        __syncthreads();
        if (issued < nst) { loadStage(issued & 3, issued * GKTW); issued++; }
        computeStage(s & 3);
    }

    #pragma unroll
    for (int mi = 0; mi < 4; mi++) {
        #pragma unroll
        for (int ni = 0; ni < 4; ni++) {
            int r0 = rowBase + wm + mi * 16 + g;
            int c0 = colBase + wn + ni * 8 + 2 * t;   // even
            if (c0 < N) {
                float bx = bias[c0], by = bias[c0 + 1];
                float v00 = acc[mi][ni][0] + bx;
                float v01 = acc[mi][ni][1] + by;
                float v10 = acc[mi][ni][2] + bx;
                float v11 = acc[mi][ni][3] + by;
                if (OM == 0) {
                    float* C = (float*)Cv;
                    float2 ra = *(const float2*)&R[(size_t)r0 * N + c0];
                    float2 rb = *(const float2*)&R[(size_t)(r0 + 8) * N + c0];
                    *(float2*)&C[(size_t)r0 * N + c0]       = make_float2(v00 + ra.x, v01 + ra.y);
                    *(float2*)&C[(size_t)(r0 + 8) * N + c0] = make_float2(v10 + rb.x, v11 + rb.y);
                } else if (OM == 4) {
                    float* C = (float*)Cv;
                    *(float2*)&C[(size_t)r0 * N + c0]       = make_float2(v00, v01);
                    *(float2*)&C[(size_t)(r0 + 8) * N + c0] = make_float2(v10, v11);
                } else {
                    if (OM == 2) {
                        v00 = fmaxf(v00, 0.f); v01 = fmaxf(v01, 0.f);
                        v10 = fmaxf(v10, 0.f); v11 = fmaxf(v11, 0.f);
                    }
                    if (OM == 3 && c0 < Hd) {
                        v00 *= 0.125f; v01 *= 0.125f;
                        v10 *= 0.125f; v11 *= 0.125f;
                    }
                    unsigned* C = (unsigned*)Cv;
                    int n2 = N >> 1;
                    C[(size_t)r0 * n2 + (c0 >> 1)]       = pack2(v00, v01);
                    C[(size_t)(r0 + 8) * n2 + (c0 >> 1)] = pack2(v10, v11);
                }
            }
        }
    }
}

// ============================================================================
// fp16 flash attention (unchanged from R13: 3-buffer ring, 1 sync/tile,
// register-resident P, direct V gather via byte_perm)
// ============================================================================
#define KPAD 36
#define VPAD 36
#define FLASH_SMEM ((3*128*KPAD + 3*128*VPAD) * 4 + 512)

__global__ void __launch_bounds__(256, 1)
flash_attn(const unsigned* __restrict__ qkv,
           const unsigned char* __restrict__ mask,
           unsigned* __restrict__ ctx)
{
    extern __shared__ unsigned fsm[];
    unsigned* Ks = fsm;                         // [3][128][KPAD]
    unsigned* Vs = Ks + 3*128*KPAD;             // [3][128][VPAD]
    unsigned char* Ms = (unsigned char*)(Vs + 3*128*VPAD);   // 3*128

    int bi = blockIdx.y;
    int b = bi >> 3, h = bi & 7;
    int qBase = blockIdx.x * 128;
    const unsigned* Qg = qkv + (size_t)b*Sd*QW2 + h*(DKd/2);
    const unsigned* Kg = qkv + (size_t)b*Sd*QW2 + HW2     + h*(DKd/2);
    const unsigned* Vg = qkv + (size_t)b*Sd*QW2 + 2*HW2   + h*(DKd/2);
    const unsigned char* mr = mask + (size_t)b*Sd;
    unsigned* Cg = ctx + (size_t)b*Sd*HW2 + h*(DKd/2);

    int tid = threadIdx.x;
    int wid = tid >> 5, lane = tid & 31;
    int g = lane >> 2, t = lane & 3;
    int wm = wid * 16;

    unsigned qf[4][4];
    {
        int r0 = qBase + wm + g, r1 = r0 + 8;
        #pragma unroll
        for (int c = 0; c < 4; c++) {
            qf[c][0] = Qg[(size_t)r0*QW2 + c*8 + t];
            qf[c][1] = Qg[(size_t)r1*QW2 + c*8 + t];
            qf[c][2] = Qg[(size_t)r0*QW2 + c*8 + 4 + t];
            qf[c][3] = Qg[(size_t)r1*QW2 + c*8 + 4 + t];
        }
    }

    float m0 = -1e30f, m1 = -1e30f, l0 = 0.f, l1 = 0.f;
    float o[8][4];
    #pragma unroll
    for (int i = 0; i < 8; i++)
        #pragma unroll
        for (int r = 0; r < 4; r++) o[i][r] = 0.f;

    auto loadTile = [&](int kt, int buf) {
        unsigned* Ktile = Ks + buf*128*KPAD;
        unsigned* Vtile = Vs + buf*128*VPAD;
        #pragma unroll
        for (int i = 0; i < 4; i++) {
            int li = tid + i * 256;
            int r = li >> 3, cq = (li & 7) * 4;
            cpa16((unsigned)__cvta_generic_to_shared(&Ktile[r*KPAD + cq]),
                  &Kg[(size_t)(kt*128 + r)*QW2 + cq]);
            cpa16((unsigned)__cvta_generic_to_shared(&Vtile[r*VPAD + cq]),
                  &Vg[(size_t)(kt*128 + r)*QW2 + cq]);
        }
        if (tid < 32) {
            uchar4 mv = *(const uchar4*)&mr[kt*128 + tid*4];
            *(uchar4*)&Ms[buf*128 + tid*4] = mv;
        }
        cp_commit();
    };

    const int NT = Sd / 128;   // 16
    loadTile(0, 0);

    for (int kt = 0; kt < NT; kt++) {
        int buf = kt % 3;
        if (kt + 1 < NT) { loadTile(kt + 1, (kt + 1) % 3); cp_wait<1>(); }
        else             { cp_wait<0>(); }
        __syncthreads();   // tile kt visible; bounds warp drift to 1 iter

        const unsigned* Ktile = Ks + buf*128*KPAD;
        const unsigned* Vtile = Vs + buf*128*VPAD;
        const unsigned char* Mt = Ms + buf*128;

        // ---- S = Q K^T ----
        float s[16][4];
        #pragma unroll
        for (int ni = 0; ni < 16; ni++)
            #pragma unroll
            for (int r = 0; r < 4; r++) s[ni][r] = 0.f;

        #pragma unroll
        for (int c = 0; c < 4; c++) {
            #pragma unroll
            for (int ni = 0; ni < 16; ni++) {
                int n = ni*8 + g;
                unsigned b0 = Ktile[n*KPAD + c*8 + t];
                unsigned b1 = Ktile[n*KPAD + c*8 + 4 + t];
                mma16(s[ni], qf[c][0], qf[c][1], qf[c][2], qf[c][3], b0, b1);
            }
        }

        // ---- mask + row max ----
        float mt0 = -1e30f, mt1 = -1e30f;
        #pragma unroll
        for (int ni = 0; ni < 16; ni++) {
            int c = ni*8 + 2*t;
            if (Mt[c])     { s[ni][0] = -1e30f; s[ni][2] = -1e30f; }
            if (Mt[c + 1]) { s[ni][1] = -1e30f; s[ni][3] = -1e30f; }
            mt0 = fmaxf(mt0, fmaxf(s[ni][0], s[ni][1]));
            mt1 = fmaxf(mt1, fmaxf(s[ni][2], s[ni][3]));
        }
        mt0 = fmaxf(mt0, __shfl_xor_sync(0xffffffffu, mt0, 1));
        mt0 = fmaxf(mt0, __shfl_xor_sync(0xffffffffu, mt0, 2));
        mt1 = fmaxf(mt1, __shfl_xor_sync(0xffffffffu, mt1, 1));
        mt1 = fmaxf(mt1, __shfl_xor_sync(0xffffffffu, mt1, 2));

        float mn0 = fmaxf(m0, mt0), mn1 = fmaxf(m1, mt1);
        float c0s = __expf(m0 - mn0), c1s = __expf(m1 - mn1);
        m0 = mn0; m1 = mn1;

        // ---- exp in-place + row sums ----
        float rs0 = 0.f, rs1 = 0.f;
        #pragma unroll
        for (int ni = 0; ni < 16; ni++) {
            s[ni][0] = __expf(s[ni][0] - m0);
            s[ni][1] = __expf(s[ni][1] - m0);
            s[ni][2] = __expf(s[ni][2] - m1);
            s[ni][3] = __expf(s[ni][3] - m1);
            rs0 += s[ni][0] + s[ni][1];
            rs1 += s[ni][2] + s[ni][3];
        }
        rs0 += __shfl_xor_sync(0xffffffffu, rs0, 1);
        rs0 += __shfl_xor_sync(0xffffffffu, rs0, 2);
        rs1 += __shfl_xor_sync(0xffffffffu, rs1, 1);
        rs1 += __shfl_xor_sync(0xffffffffu, rs1, 2);
        l0 = l0 * c0s + rs0;
        l1 = l1 * c1s + rs1;

        #pragma unroll
        for (int oni = 0; oni < 8; oni++) {
            o[oni][0] *= c0s; o[oni][1] *= c0s;
            o[oni][2] *= c1s; o[oni][3] *= c1s;
        }

        // ---- O += P V ----
        {
            unsigned sel = (g & 1) ? 0x7632u : 0x5410u;
            #pragma unroll
            for (int kk = 0; kk < 8; kk++) {
                unsigned a0 = pack2(s[2*kk][0],   s[2*kk][1]);
                unsigned a1 = pack2(s[2*kk][2],   s[2*kk][3]);
                unsigned a2 = pack2(s[2*kk+1][0], s[2*kk+1][1]);
                unsigned a3 = pack2(s[2*kk+1][2], s[2*kk+1][3]);
                const unsigned* V0a = Vtile + (2*(kk*8 + t))*VPAD;
                const unsigned* V0b = V0a + VPAD;
                const unsigned* V1a = Vtile + (2*(kk*8 + 4 + t))*VPAD;
                const unsigned* V1b = V1a + VPAD;
                #pragma unroll
                for (int oni = 0; oni < 8; oni++) {
                    int dw = oni*4 + (g >> 1);
                    unsigned b0 = __byte_perm(V0a[dw], V0b[dw], sel);
                    unsigned b1 = __byte_perm(V1a[dw], V1b[dw], sel);
                    mma16(o[oni], a0, a1, a2, a3, b0, b1);
                }
            }
        }
    }

    // ---- epilogue ----
    float i0 = 1.f / l0, i1 = 1.f / l1;
    int r0 = qBase + wm + g, r1 = r0 + 8;
    #pragma unroll
    for (int oni = 0; oni < 8; oni++) {
        int wrd = oni*4 + t;
        Cg[(size_t)r0*HW2 + wrd] = pack2(o[oni][0] * i0, o[oni][1] * i0);
        Cg[(size_t)r1*HW2 + wrd] = pack2(o[oni][2] * i1, o[oni][3] * i1);
    }
}

// ---------------- launch ----------------
extern "C" void kernel_launch(void* const* d_in, const int* in_sizes, int n_in,
                              void* d_out, int out_size)
{
    const int*           src  = (const int*)d_in[0];
    const unsigned char* mask = (const unsigned char*)d_in[1];
    const float* emb  = (const float*)d_in[2];
    const float* Wq   = (const float*)d_in[3];
    const float* bq   = (const float*)d_in[4];
    const float* Wk   = (const float*)d_in[5];
    const float* bk   = (const float*)d_in[6];
    const float* Wv   = (const float*)d_in[7];
    const float* bv   = (const float*)d_in[8];
    const float* Wo   = (const float*)d_in[9];
    const float* bo   = (const float*)d_in[10];
    const float* ln1g = (const float*)d_in[11];
    const float* ln1b = (const float*)d_in[12];
    const float* W1   = (const float*)d_in[13];
    const float* b1   = (const float*)d_in[14];
    const float* W2   = (const float*)d_in[15];
    const float* b2   = (const float*)d_in[16];
    const float* ln2g = (const float*)d_in[17];
    const float* ln2b = (const float*)d_in[18];
    const float* lnfg = (const float*)d_in[19];
    const float* lnfb = (const float*)d_in[20];
    const float* Wg   = (const float*)d_in[21];
    const float* bg   = (const float*)d_in[22];
    float* out = (float*)d_out;

    float *x;   unsigned *h, *qkv, *ctx, *ff;
    unsigned *wqkv, *wo, *w1, *w2, *wg;  float *bqkv;
    cudaGetSymbolAddress((void**)&x,    g_x);
    cudaGetSymbolAddress((void**)&h,    g_h);
    cudaGetSymbolAddress((void**)&qkv,  g_qkv);
    cudaGetSymbolAddress((void**)&ctx,  g_ctx);
    cudaGetSymbolAddress((void**)&ff,   g_ff);
    cudaGetSymbolAddress((void**)&wqkv, g_wqkv);
    cudaGetSymbolAddress((void**)&wo,   g_wo);
    cudaGetSymbolAddress((void**)&w1,   g_w1);
    cudaGetSymbolAddress((void**)&w2,   g_w2);
    cudaGetSymbolAddress((void**)&wg,   g_wg);
    cudaGetSymbolAddress((void**)&bqkv, g_bqkv);

    static bool attr_set = false;
    if (!attr_set) {
        cudaFuncSetAttribute(flash_attn,
                             cudaFuncAttributeMaxDynamicSharedMemorySize, FLASH_SMEM);
        cudaFuncSetAttribute(gemm_hk<0>,
                             cudaFuncAttributeMaxDynamicSharedMemorySize, GEMM_SMEM);
        cudaFuncSetAttribute(gemm_hk<2>,
                             cudaFuncAttributeMaxDynamicSharedMemorySize, GEMM_SMEM);
        cudaFuncSetAttribute(gemm_hk<3>,
                             cudaFuncAttributeMaxDynamicSharedMemorySize, GEMM_SMEM);
        cudaFuncSetAttribute(gemm_hk<4>,
                             cudaFuncAttributeMaxDynamicSharedMemorySize, GEMM_SMEM);
        attr_set = true;
    }

    // ---- prepack weights to half2 words ----
    pack_qkv_kernel<<<1184, 256>>>(Wq, Wk, Wv, wqkv);
    pack_bqkv_kernel<<<(Lx*QKVW + 255)/256, 256>>>(bq, bk, bv, bqkv);
    conv_pack<<<1184, 256>>>(Wo, wo, Hd,    Lx*HW2*Hd);
    conv_pack<<<1184, 256>>>(W1, w1, FFd,   Lx*HW2*FFd);
    conv_pack<<<1184, 256>>>(W2, w2, Hd,    Lx*FW2*Hd);
    conv_pack<<<1184, 256>>>(Wg, wg, Vocab, HW2*Vocab);

    embed_kernel<<<(Nt*Hd + 255)/256, 256>>>(src, emb, x);

    dim3 gQKV(QKVW/128, Nt/128);
    dim3 gH(Hd/128,  Nt/128);
    dim3 gF(FFd/128, Nt/128);
    dim3 gV((Vocab+127)/128, Nt/128);

    for (int l = 0; l < Lx; l++) {
        layernorm_kernel<<<Nt/8, 256>>>(x, ln1g + (size_t)l*Hd, ln1b + (size_t)l*Hd, h);

        // fused QKV (q cols pre-scaled by 1/8, half2 out)
        gemm_hk<3><<<gQKV, 256, GEMM_SMEM>>>(h, wqkv + (size_t)l*HW2*QKVW, bqkv + (size_t)l*QKVW,
                                             nullptr, qkv, Nt, QKVW, HW2);

        flash_attn<<<dim3(Sd/128, Bd*NHd), 256, FLASH_SMEM>>>(qkv, mask, ctx);

        // x = x + ctx @ Wo + bo
        gemm_hk<0><<<gH, 256, GEMM_SMEM>>>(ctx, wo + (size_t)l*HW2*Hd, bo + (size_t)l*Hd,
                                           x, x, Nt, Hd, HW2);

        layernorm_kernel<<<Nt/8, 256>>>(x, ln2g + (size_t)l*Hd, ln2b + (size_t)l*Hd, h);

        // ff = relu(h @ W1 + b1) (half2 out)
        gemm_hk<2><<<gF, 256, GEMM_SMEM>>>(h, w1 + (size_t)l*HW2*FFd, b1 + (size_t)l*FFd,
                                           nullptr, ff, Nt, FFd, HW2);
        // x = x + ff @ W2 + b2
        gemm_hk<0><<<gH, 256, GEMM_SMEM>>>(ff, w2 + (size_t)l*FW2*Hd, b2 + (size_t)l*Hd,
                                           x, x, Nt, Hd, FW2);
    }

    layernorm_kernel<<<Nt/8, 256>>>(x, lnfg, lnfb, h);
    gemm_hk<4><<<gV, 256, GEMM_SMEM>>>(h, wg, bg, nullptr, out, Nt, Vocab, HW2);
}

// round 15
// speedup vs baseline: 1.0483x; 1.0483x over previous
#include <cuda_runtime.h>
#include <cuda_fp16.h>
#include <math.h>

// Problem constants
#define Lx  6
#define Hd  512
#define NHd 8
#define FFd 2048
#define Vocab 10000
#define Bd  4
#define Sd  2048
#define DKd 64
#define Nt  (Bd*Sd)     // 8192 tokens
#define QKVW 1536       // fused QKV width
#define QW2 768         // QKVW/2 words
#define HW2 256         // Hd/2 words
#define FW2 1024        // FFd/2 words

// ---------------- scratch (static device globals; no runtime alloc) ----------------
__device__ float    g_x[Nt*Hd];           // fp32 running activations
__device__ unsigned g_h[Nt*HW2];          // half2-packed LN output
__device__ unsigned g_qkv[Nt*QW2];        // half2-packed fused q|k|v
__device__ unsigned g_ctx[Nt*HW2];        // half2-packed attention output
__device__ unsigned g_ff[Nt*FW2];         // half2-packed FFN hidden
// prepacked fp16 weights: [K/2 words][N], word = half2(W[2k][n], W[2k+1][n])
__device__ unsigned g_wqkv[Lx*HW2*QKVW];
__device__ unsigned g_wo[Lx*HW2*Hd];
__device__ unsigned g_w1[Lx*HW2*FFd];
__device__ unsigned g_w2[Lx*FW2*Hd];
__device__ unsigned g_wg[HW2*Vocab];
__device__ float    g_bqkv[Lx*QKVW];

// ---------------- helpers ----------------
__device__ __forceinline__ unsigned pack2(float a, float b) {
    __half2 h2 = __floats2half2_rn(a, b);   // .x = low = a
    return *reinterpret_cast<unsigned*>(&h2);
}

__device__ __forceinline__ void mma16(float* c,
                                      unsigned a0, unsigned a1, unsigned a2, unsigned a3,
                                      unsigned b0, unsigned b1) {
    asm volatile(
        "mma.sync.aligned.m16n8k16.row.col.f32.f16.f16.f32 "
        "{%0,%1,%2,%3}, {%4,%5,%6,%7}, {%8,%9}, {%0,%1,%2,%3};"
        : "+f"(c[0]), "+f"(c[1]), "+f"(c[2]), "+f"(c[3])
        : "r"(a0), "r"(a1), "r"(a2), "r"(a3), "r"(b0), "r"(b1));
}

__device__ __forceinline__ void cpa16(unsigned dst, const void* src) {
    asm volatile("cp.async.ca.shared.global [%0], [%1], 16;" :: "r"(dst), "l"(src));
}
__device__ __forceinline__ void cpa16p(unsigned dst, const void* src, int bytes) {
    asm volatile("cp.async.ca.shared.global [%0], [%1], 16, %2;" :: "r"(dst), "l"(src), "r"(bytes));
}
__device__ __forceinline__ void cp_commit() { asm volatile("cp.async.commit_group;"); }
template<int N> __device__ __forceinline__ void cp_wait() {
    asm volatile("cp.async.wait_group %0;" :: "n"(N));
}

// ---------------- weight prepack (vectorized): fp32 [rows][N] -> half2 [rows/2][N] ----------------
__global__ void conv_pack(const float* __restrict__ src,
                          unsigned* __restrict__ dst, int N, int totalWords)
{
    int N4 = N >> 2;
    int totalQ = totalWords >> 2;
    for (int q = blockIdx.x * blockDim.x + threadIdx.x;
         q < totalQ; q += gridDim.x * blockDim.x) {
        int r2 = q / N4, n4 = q - r2 * N4;
        const float4 a = *(const float4*)&src[(size_t)(2*r2)*N + n4*4];
        const float4 c = *(const float4*)&src[(size_t)(2*r2+1)*N + n4*4];
        uint4 w;
        w.x = pack2(a.x, c.x);
        w.y = pack2(a.y, c.y);
        w.z = pack2(a.z, c.z);
        w.w = pack2(a.w, c.w);
        *(uint4*)&dst[(size_t)q*4] = w;
    }
}

__global__ void pack_qkv_kernel(const float* __restrict__ Wq,
                                const float* __restrict__ Wk,
                                const float* __restrict__ Wv,
                                unsigned* __restrict__ dst)
{
    const int N4 = QKVW >> 2;
    int totalQ = Lx*HW2*N4;
    for (int q = blockIdx.x * blockDim.x + threadIdx.x;
         q < totalQ; q += gridDim.x * blockDim.x) {
        int l = q / (HW2*N4);
        int rem = q - l * HW2*N4;
        int k2 = rem / N4;
        int n = (rem - k2 * N4) * 4;
        const float* Wm; int nn;
        if (n < Hd)        { Wm = Wq; nn = n; }
        else if (n < 2*Hd) { Wm = Wk; nn = n - Hd; }
        else               { Wm = Wv; nn = n - 2*Hd; }
        const float4 a = *(const float4*)&Wm[(size_t)l*Hd*Hd + (size_t)(2*k2)*Hd + nn];
        const float4 c = *(const float4*)&Wm[(size_t)l*Hd*Hd + (size_t)(2*k2+1)*Hd + nn];
        uint4 w;
        w.x = pack2(a.x, c.x);
        w.y = pack2(a.y, c.y);
        w.z = pack2(a.z, c.z);
        w.w = pack2(a.w, c.w);
        *(uint4*)&dst[((size_t)l*HW2 + k2)*QKVW + n] = w;
    }
}

__global__ void pack_bqkv_kernel(const float* __restrict__ bq,
                                 const float* __restrict__ bk,
                                 const float* __restrict__ bv,
                                 float* __restrict__ dst)
{
    int idx = blockIdx.x * blockDim.x + threadIdx.x;
    if (idx >= Lx*QKVW) return;
    int l = idx / QKVW;
    int n = idx - l * QKVW;
    float val;
    if (n < Hd)        val = bq[l*Hd + n];
    else if (n < 2*Hd) val = bk[l*Hd + (n - Hd)];
    else               val = bv[l*Hd + (n - 2*Hd)];
    dst[idx] = val;
}

// ---------------- embedding + sinusoidal positional encoding ----------------
__global__ void embed_kernel(const int* __restrict__ src,
                             const float* __restrict__ emb,
                             float* __restrict__ x)
{
    int idx = blockIdx.x * blockDim.x + threadIdx.x;
    if (idx >= Nt*Hd) return;
    int n = idx >> 9;
    int c = idx & (Hd-1);
    int s = n & (Sd-1);
    int tok = src[n];
    int i2 = c & ~1;
    float div = expf(-(logf(10000.0f)/(float)Hd) * (float)i2);
    float ang = (float)s * div;
    float pe = (c & 1) ? cosf(ang) : sinf(ang);
    x[idx] = emb[(size_t)tok*Hd + c] + pe;
}

// ---------------- layernorm: warp per row, no block sync. fp32 in -> half2 out ----------------
__global__ void layernorm_kernel(const float* __restrict__ x,
                                 const float* __restrict__ g,
                                 const float* __restrict__ b,
                                 unsigned* __restrict__ out)
{
    int wid = threadIdx.x >> 5, lane = threadIdx.x & 31;
    int row = blockIdx.x * 8 + wid;
    const float* xr = x + (size_t)row*Hd;

    float4 v[4];
    #pragma unroll
    for (int ch = 0; ch < 4; ch++)
        v[ch] = *(const float4*)(xr + ch*128 + lane*4);

    float s = 0.f;
    #pragma unroll
    for (int ch = 0; ch < 4; ch++) s += v[ch].x + v[ch].y + v[ch].z + v[ch].w;
    #pragma unroll
    for (int o = 16; o > 0; o >>= 1) s += __shfl_xor_sync(0xffffffffu, s, o);
    float mean = s * (1.0f/(float)Hd);

    float ss = 0.f;
    #pragma unroll
    for (int ch = 0; ch < 4; ch++) {
        float dx = v[ch].x - mean, dy = v[ch].y - mean;
        float dz = v[ch].z - mean, dw = v[ch].w - mean;
        ss += dx*dx + dy*dy + dz*dz + dw*dw;
    }
    #pragma unroll
    for (int o = 16; o > 0; o >>= 1) ss += __shfl_xor_sync(0xffffffffu, ss, o);
    float rstd = rsqrtf(ss * (1.0f/(float)Hd) + 1e-5f);

    #pragma unroll
    for (int ch = 0; ch < 4; ch++) {
        int c = ch*128 + lane*4;
        float4 gg = *(const float4*)(g + c);
        float4 bb = *(const float4*)(b + c);
        float o0 = (v[ch].x - mean)*rstd*gg.x + bb.x;
        float o1 = (v[ch].y - mean)*rstd*gg.y + bb.y;
        float o2 = (v[ch].z - mean)*rstd*gg.z + bb.z;
        float o3 = (v[ch].w - mean)*rstd*gg.w + bb.w;
        uint2 w2 = make_uint2(pack2(o0, o1), pack2(o2, o3));
        *(uint2*)(out + (size_t)row*HW2 + (c >> 1)) = w2;
    }
}

// ============================================================================
// fp16 GEMM (R13 schedule: 3-stage, compute-then-prefetch).
// A [M][K2] half2 words (k-pairs), B [K2][N] half2 words.
// OUT modes: 0 = f32 + residual, 2 = half2+relu,
//            3 = half2 with cols<Hd scaled 0.125 (fused QKV), 4 = f32 plain
// ============================================================================
#define GKTW 16     // k-words per stage (32 k)
#define APAD 20
#define BPAD 136
#define GEMM_SMEM ((3*128*APAD + 3*GKTW*BPAD) * 4)

template<int OM>
__global__ void __launch_bounds__(256, 2)
gemm_hk(const unsigned* __restrict__ A,
        const unsigned* __restrict__ B,
        const float* __restrict__ bias,
        const float* __restrict__ R,
        void* __restrict__ Cv,
        int M, int N, int K2)
{
    extern __shared__ unsigned gsm[];
    unsigned* As = gsm;                 // [3][128][APAD]
    unsigned* Bs = gsm + 3*128*APAD;    // [3][GKTW][BPAD]

    int tid = threadIdx.x;
    int wid = tid >> 5, lane = tid & 31;
    int g = lane >> 2, t = lane & 3;
    int wm = (wid >> 2) * 64;
    int wn = (wid & 3) * 32;
    int rowBase = blockIdx.y * 128;
    int colBase = blockIdx.x * 128;

    float acc[4][4][4];
    #pragma unroll
    for (int mi = 0; mi < 4; mi++)
        #pragma unroll
        for (int ni = 0; ni < 4; ni++)
            #pragma unroll
            for (int r = 0; r < 4; r++) acc[mi][ni][r] = 0.0f;

    int nst = K2 / GKTW;

    auto loadStage = [&](int st, int k0w) {
        unsigned* Adst = As + st*128*APAD;
        unsigned* Bdst = Bs + st*GKTW*BPAD;
        #pragma unroll
        for (int i = 0; i < 2; i++) {
            int li = tid + i * 256;
            int r = li >> 2, kq = (li & 3) * 4;
            cpa16((unsigned)__cvta_generic_to_shared(&Adst[r*APAD + kq]),
                  &A[(size_t)(rowBase + r) * K2 + k0w + kq]);
        }
        #pragma unroll
        for (int i = 0; i < 2; i++) {
            int li = tid + i * 256;
            int r = li >> 5, cq = (li & 31) * 4;
            int gc = colBase + cq;
            cpa16p((unsigned)__cvta_generic_to_shared(&Bdst[r*BPAD + cq]),
                   &B[(size_t)(k0w + r) * N + gc], (gc + 4 <= N) ? 16 : 0);
        }
        cp_commit();
    };

    auto computeStage = [&](int st) {
        const unsigned* Asrc = As + st*128*APAD;
        const unsigned* Bsrc = Bs + st*GKTW*BPAD;
        #pragma unroll
        for (int kk2 = 0; kk2 < GKTW; kk2 += 8) {   // 2 x k16 chunks
            unsigned a[4][4], b[4][2];
            #pragma unroll
            for (int mi = 0; mi < 4; mi++) {
                int m = wm + mi * 16 + g;
                a[mi][0] = Asrc[m*APAD       + kk2 + t];
                a[mi][1] = Asrc[(m + 8)*APAD + kk2 + t];
                a[mi][2] = Asrc[m*APAD       + kk2 + 4 + t];
                a[mi][3] = Asrc[(m + 8)*APAD + kk2 + 4 + t];
            }
            #pragma unroll
            for (int ni = 0; ni < 4; ni++) {
                int n = wn + ni * 8 + g;
                b[ni][0] = Bsrc[(kk2 + t)*BPAD     + n];
                b[ni][1] = Bsrc[(kk2 + 4 + t)*BPAD + n];
            }
            #pragma unroll
            for (int mi = 0; mi < 4; mi++)
                #pragma unroll
                for (int ni = 0; ni < 4; ni++)
                    mma16(acc[mi][ni], a[mi][0], a[mi][1], a[mi][2], a[mi][3],
                          b[ni][0], b[ni][1]);
        }
    };

    loadStage(0, 0);
    if (nst > 1) loadStage(1, GKTW);

    for (int s = 0; s < nst; s++) {
        if (s + 1 < nst) cp_wait<1>(); else cp_wait<0>();
        __syncthreads();
        computeStage(s % 3);
        if (s + 2 < nst) loadStage((s + 2) % 3, (s + 2) * GKTW);
    }

    #pragma unroll
    for (int mi = 0; mi < 4; mi++) {
        #pragma unroll
        for (int ni = 0; ni < 4; ni++) {
            int r0 = rowBase + wm + mi * 16 + g;
            int c0 = colBase + wn + ni * 8 + 2 * t;   // even
            if (c0 < N) {
                float bx = bias[c0], by = bias[c0 + 1];
                float v00 = acc[mi][ni][0] + bx;
                float v01 = acc[mi][ni][1] + by;
                float v10 = acc[mi][ni][2] + bx;
                float v11 = acc[mi][ni][3] + by;
                if (OM == 0) {
                    float* C = (float*)Cv;
                    float2 ra = *(const float2*)&R[(size_t)r0 * N + c0];
                    float2 rb = *(const float2*)&R[(size_t)(r0 + 8) * N + c0];
                    *(float2*)&C[(size_t)r0 * N + c0]       = make_float2(v00 + ra.x, v01 + ra.y);
                    *(float2*)&C[(size_t)(r0 + 8) * N + c0] = make_float2(v10 + rb.x, v11 + rb.y);
                } else if (OM == 4) {
                    float* C = (float*)Cv;
                    *(float2*)&C[(size_t)r0 * N + c0]       = make_float2(v00, v01);
                    *(float2*)&C[(size_t)(r0 + 8) * N + c0] = make_float2(v10, v11);
                } else {
                    if (OM == 2) {
                        v00 = fmaxf(v00, 0.f); v01 = fmaxf(v01, 0.f);
                        v10 = fmaxf(v10, 0.f); v11 = fmaxf(v11, 0.f);
                    }
                    if (OM == 3 && c0 < Hd) {
                        v00 *= 0.125f; v01 *= 0.125f;
                        v10 *= 0.125f; v11 *= 0.125f;
                    }
                    unsigned* C = (unsigned*)Cv;
                    int n2 = N >> 1;
                    C[(size_t)r0 * n2 + (c0 >> 1)]       = pack2(v00, v01);
                    C[(size_t)(r0 + 8) * n2 + (c0 >> 1)] = pack2(v10, v11);
                }
            }
        }
    }
}

// ============================================================================
// fp16 flash attention (R13: 3-buffer ring, 1 sync/tile, register P,
// direct V gather via byte_perm)
// ============================================================================
#define KPAD 36
#define VPAD 36
#define FLASH_SMEM ((3*128*KPAD + 3*128*VPAD) * 4 + 512)

__global__ void __launch_bounds__(256, 1)
flash_attn(const unsigned* __restrict__ qkv,
           const unsigned char* __restrict__ mask,
           unsigned* __restrict__ ctx)
{
    extern __shared__ unsigned fsm[];
    unsigned* Ks = fsm;                         // [3][128][KPAD]
    unsigned* Vs = Ks + 3*128*KPAD;             // [3][128][VPAD]
    unsigned char* Ms = (unsigned char*)(Vs + 3*128*VPAD);   // 3*128

    int bi = blockIdx.y;
    int b = bi >> 3, h = bi & 7;
    int qBase = blockIdx.x * 128;
    const unsigned* Qg = qkv + (size_t)b*Sd*QW2 + h*(DKd/2);
    const unsigned* Kg = qkv + (size_t)b*Sd*QW2 + HW2     + h*(DKd/2);
    const unsigned* Vg = qkv + (size_t)b*Sd*QW2 + 2*HW2   + h*(DKd/2);
    const unsigned char* mr = mask + (size_t)b*Sd;
    unsigned* Cg = ctx + (size_t)b*Sd*HW2 + h*(DKd/2);

    int tid = threadIdx.x;
    int wid = tid >> 5, lane = tid & 31;
    int g = lane >> 2, t = lane & 3;
    int wm = wid * 16;

    unsigned qf[4][4];
    {
        int r0 = qBase + wm + g, r1 = r0 + 8;
        #pragma unroll
        for (int c = 0; c < 4; c++) {
            qf[c][0] = Qg[(size_t)r0*QW2 + c*8 + t];
            qf[c][1] = Qg[(size_t)r1*QW2 + c*8 + t];
            qf[c][2] = Qg[(size_t)r0*QW2 + c*8 + 4 + t];
            qf[c][3] = Qg[(size_t)r1*QW2 + c*8 + 4 + t];
        }
    }

    float m0 = -1e30f, m1 = -1e30f, l0 = 0.f, l1 = 0.f;
    float o[8][4];
    #pragma unroll
    for (int i = 0; i < 8; i++)
        #pragma unroll
        for (int r = 0; r < 4; r++) o[i][r] = 0.f;

    auto loadTile = [&](int kt, int buf) {
        unsigned* Ktile = Ks + buf*128*KPAD;
        unsigned* Vtile = Vs + buf*128*VPAD;
        #pragma unroll
        for (int i = 0; i < 4; i++) {
            int li = tid + i * 256;
            int r = li >> 3, cq = (li & 7) * 4;
            cpa16((unsigned)__cvta_generic_to_shared(&Ktile[r*KPAD + cq]),
                  &Kg[(size_t)(kt*128 + r)*QW2 + cq]);
            cpa16((unsigned)__cvta_generic_to_shared(&Vtile[r*VPAD + cq]),
                  &Vg[(size_t)(kt*128 + r)*QW2 + cq]);
        }
        if (tid < 32) {
            uchar4 mv = *(const uchar4*)&mr[kt*128 + tid*4];
            *(uchar4*)&Ms[buf*128 + tid*4] = mv;
        }
        cp_commit();
    };

    const int NT = Sd / 128;   // 16
    loadTile(0, 0);

    for (int kt = 0; kt < NT; kt++) {
        int buf = kt % 3;
        if (kt + 1 < NT) { loadTile(kt + 1, (kt + 1) % 3); cp_wait<1>(); }
        else             { cp_wait<0>(); }
        __syncthreads();   // tile kt visible; bounds warp drift to 1 iter

        const unsigned* Ktile = Ks + buf*128*KPAD;
        const unsigned* Vtile = Vs + buf*128*VPAD;
        const unsigned char* Mt = Ms + buf*128;

        // ---- S = Q K^T ----
        float s[16][4];
        #pragma unroll
        for (int ni = 0; ni < 16; ni++)
            #pragma unroll
            for (int r = 0; r < 4; r++) s[ni][r] = 0.f;

        #pragma unroll
        for (int c = 0; c < 4; c++) {
            #pragma unroll
            for (int ni = 0; ni < 16; ni++) {
                int n = ni*8 + g;
                unsigned b0 = Ktile[n*KPAD + c*8 + t];
                unsigned b1 = Ktile[n*KPAD + c*8 + 4 + t];
                mma16(s[ni], qf[c][0], qf[c][1], qf[c][2], qf[c][3], b0, b1);
            }
        }

        // ---- mask + row max ----
        float mt0 = -1e30f, mt1 = -1e30f;
        #pragma unroll
        for (int ni = 0; ni < 16; ni++) {
            int c = ni*8 + 2*t;
            if (Mt[c])     { s[ni][0] = -1e30f; s[ni][2] = -1e30f; }
            if (Mt[c + 1]) { s[ni][1] = -1e30f; s[ni][3] = -1e30f; }
            mt0 = fmaxf(mt0, fmaxf(s[ni][0], s[ni][1]));
            mt1 = fmaxf(mt1, fmaxf(s[ni][2], s[ni][3]));
        }
        mt0 = fmaxf(mt0, __shfl_xor_sync(0xffffffffu, mt0, 1));
        mt0 = fmaxf(mt0, __shfl_xor_sync(0xffffffffu, mt0, 2));
        mt1 = fmaxf(mt1, __shfl_xor_sync(0xffffffffu, mt1, 1));
        mt1 = fmaxf(mt1, __shfl_xor_sync(0xffffffffu, mt1, 2));

        float mn0 = fmaxf(m0, mt0), mn1 = fmaxf(m1, mt1);
        float c0s = __expf(m0 - mn0), c1s = __expf(m1 - mn1);
        m0 = mn0; m1 = mn1;

        // ---- exp in-place + row sums ----
        float rs0 = 0.f, rs1 = 0.f;
        #pragma unroll
        for (int ni = 0; ni < 16; ni++) {
            s[ni][0] = __expf(s[ni][0] - m0);
            s[ni][1] = __expf(s[ni][1] - m0);
            s[ni][2] = __expf(s[ni][2] - m1);
            s[ni][3] = __expf(s[ni][3] - m1);
            rs0 += s[ni][0] + s[ni][1];
            rs1 += s[ni][2] + s[ni][3];
        }
        rs0 += __shfl_xor_sync(0xffffffffu, rs0, 1);
        rs0 += __shfl_xor_sync(0xffffffffu, rs0, 2);
        rs1 += __shfl_xor_sync(0xffffffffu, rs1, 1);
        rs1 += __shfl_xor_sync(0xffffffffu, rs1, 2);
        l0 = l0 * c0s + rs0;
        l1 = l1 * c1s + rs1;

        #pragma unroll
        for (int oni = 0; oni < 8; oni++) {
            o[oni][0] *= c0s; o[oni][1] *= c0s;
            o[oni][2] *= c1s; o[oni][3] *= c1s;
        }

        // ---- O += P V ----
        {
            unsigned sel = (g & 1) ? 0x7632u : 0x5410u;
            #pragma unroll
            for (int kk = 0; kk < 8; kk++) {
                unsigned a0 = pack2(s[2*kk][0],   s[2*kk][1]);
                unsigned a1 = pack2(s[2*kk][2],   s[2*kk][3]);
                unsigned a2 = pack2(s[2*kk+1][0], s[2*kk+1][1]);
                unsigned a3 = pack2(s[2*kk+1][2], s[2*kk+1][3]);
                const unsigned* V0a = Vtile + (2*(kk*8 + t))*VPAD;
                const unsigned* V0b = V0a + VPAD;
                const unsigned* V1a = Vtile + (2*(kk*8 + 4 + t))*VPAD;
                const unsigned* V1b = V1a + VPAD;
                #pragma unroll
                for (int oni = 0; oni < 8; oni++) {
                    int dw = oni*4 + (g >> 1);
                    unsigned b0 = __byte_perm(V0a[dw], V0b[dw], sel);
                    unsigned b1 = __byte_perm(V1a[dw], V1b[dw], sel);
                    mma16(o[oni], a0, a1, a2, a3, b0, b1);
                }
            }
        }
    }

    // ---- epilogue ----
    float i0 = 1.f / l0, i1 = 1.f / l1;
    int r0 = qBase + wm + g, r1 = r0 + 8;
    #pragma unroll
    for (int oni = 0; oni < 8; oni++) {
        int wrd = oni*4 + t;
        Cg[(size_t)r0*HW2 + wrd] = pack2(o[oni][0] * i0, o[oni][1] * i0);
        Cg[(size_t)r1*HW2 + wrd] = pack2(o[oni][2] * i1, o[oni][3] * i1);
    }
}

// ---------------- launch ----------------
extern "C" void kernel_launch(void* const* d_in, const int* in_sizes, int n_in,
                              void* d_out, int out_size)
{
    const int*           src  = (const int*)d_in[0];
    const unsigned char* mask = (const unsigned char*)d_in[1];
    const float* emb  = (const float*)d_in[2];
    const float* Wq   = (const float*)d_in[3];
    const float* bq   = (const float*)d_in[4];
    const float* Wk   = (const float*)d_in[5];
    const float* bk   = (const float*)d_in[6];
    const float* Wv   = (const float*)d_in[7];
    const float* bv   = (const float*)d_in[8];
    const float* Wo   = (const float*)d_in[9];
    const float* bo   = (const float*)d_in[10];
    const float* ln1g = (const float*)d_in[11];
    const float* ln1b = (const float*)d_in[12];
    const float* W1   = (const float*)d_in[13];
    const float* b1   = (const float*)d_in[14];
    const float* W2   = (const float*)d_in[15];
    const float* b2   = (const float*)d_in[16];
    const float* ln2g = (const float*)d_in[17];
    const float* ln2b = (const float*)d_in[18];
    const float* lnfg = (const float*)d_in[19];
    const float* lnfb = (const float*)d_in[20];
    const float* Wg   = (const float*)d_in[21];
    const float* bg   = (const float*)d_in[22];
    float* out = (float*)d_out;

    float *x;   unsigned *h, *qkv, *ctx, *ff;
    unsigned *wqkv, *wo, *w1, *w2, *wg;  float *bqkv;
    cudaGetSymbolAddress((void**)&x,    g_x);
    cudaGetSymbolAddress((void**)&h,    g_h);
    cudaGetSymbolAddress((void**)&qkv,  g_qkv);
    cudaGetSymbolAddress((void**)&ctx,  g_ctx);
    cudaGetSymbolAddress((void**)&ff,   g_ff);
    cudaGetSymbolAddress((void**)&wqkv, g_wqkv);
    cudaGetSymbolAddress((void**)&wo,   g_wo);
    cudaGetSymbolAddress((void**)&w1,   g_w1);
    cudaGetSymbolAddress((void**)&w2,   g_w2);
    cudaGetSymbolAddress((void**)&wg,   g_wg);
    cudaGetSymbolAddress((void**)&bqkv, g_bqkv);

    static bool attr_set = false;
    if (!attr_set) {
        cudaFuncSetAttribute(flash_attn,
                             cudaFuncAttributeMaxDynamicSharedMemorySize, FLASH_SMEM);
        cudaFuncSetAttribute(gemm_hk<0>,
                             cudaFuncAttributeMaxDynamicSharedMemorySize, GEMM_SMEM);
        cudaFuncSetAttribute(gemm_hk<2>,
                             cudaFuncAttributeMaxDynamicSharedMemorySize, GEMM_SMEM);
        cudaFuncSetAttribute(gemm_hk<3>,
                             cudaFuncAttributeMaxDynamicSharedMemorySize, GEMM_SMEM);
        cudaFuncSetAttribute(gemm_hk<4>,
                             cudaFuncAttributeMaxDynamicSharedMemorySize, GEMM_SMEM);
        attr_set = true;
    }

    // ---- prepack weights to half2 words ----
    pack_qkv_kernel<<<1184, 256>>>(Wq, Wk, Wv, wqkv);
    pack_bqkv_kernel<<<(Lx*QKVW + 255)/256, 256>>>(bq, bk, bv, bqkv);
    conv_pack<<<1184, 256>>>(Wo, wo, Hd,    Lx*HW2*Hd);
    conv_pack<<<1184, 256>>>(W1, w1, FFd,   Lx*HW2*FFd);
    conv_pack<<<1184, 256>>>(W2, w2, Hd,    Lx*FW2*Hd);
    conv_pack<<<1184, 256>>>(Wg, wg, Vocab, HW2*Vocab);

    embed_kernel<<<(Nt*Hd + 255)/256, 256>>>(src, emb, x);

    dim3 gQKV(QKVW/128, Nt/128);
    dim3 gH(Hd/128,  Nt/128);
    dim3 gF(FFd/128, Nt/128);
    dim3 gV((Vocab+127)/128, Nt/128);

    for (int l = 0; l < Lx; l++) {
        layernorm_kernel<<<Nt/8, 256>>>(x, ln1g + (size_t)l*Hd, ln1b + (size_t)l*Hd, h);

        // fused QKV (q cols pre-scaled by 1/8, half2 out)
        gemm_hk<3><<<gQKV, 256, GEMM_SMEM>>>(h, wqkv + (size_t)l*HW2*QKVW, bqkv + (size_t)l*QKVW,
                                             nullptr, qkv, Nt, QKVW, HW2);

        flash_attn<<<dim3(Sd/128, Bd*NHd), 256, FLASH_SMEM>>>(qkv, mask, ctx);

        // x = x + ctx @ Wo + bo
        gemm_hk<0><<<gH, 256, GEMM_SMEM>>>(ctx, wo + (size_t)l*HW2*Hd, bo + (size_t)l*Hd,
                                           x, x, Nt, Hd, HW2);

        layernorm_kernel<<<Nt/8, 256>>>(x, ln2g + (size_t)l*Hd, ln2b + (size_t)l*Hd, h);

        // ff = relu(h @ W1 + b1) (half2 out)
        gemm_hk<2><<<gF, 256, GEMM_SMEM>>>(h, w1 + (size_t)l*HW2*FFd, b1 + (size_t)l*FFd,
                                           nullptr, ff, Nt, FFd, HW2);
        // x = x + ff @ W2 + b2
        gemm_hk<0><<<gH, 256, GEMM_SMEM>>>(ff, w2 + (size_t)l*FW2*Hd, b2 + (size_t)l*Hd,
                                           x, x, Nt, Hd, FW2);
    }

    layernorm_kernel<<<Nt/8, 256>>>(x, lnfg, lnfb, h);
    gemm_hk<4><<<gV, 256, GEMM_SMEM>>>(h, wg, bg, nullptr, out, Nt, Vocab, HW2);
}

// round 16
// speedup vs baseline: 1.0545x; 1.0060x over previous
#include <cuda_runtime.h>
#include <cuda_fp16.h>
#include <math.h>

// Problem constants
#define Lx  6
#define Hd  512
#define NHd 8
#define FFd 2048
#define Vocab 10000
#define Bd  4
#define Sd  2048
#define DKd 64
#define Nt  (Bd*Sd)     // 8192 tokens
#define QKVW 1536       // fused QKV width
#define QW2 768         // QKVW/2 words
#define HW2 256         // Hd/2 words
#define FW2 1024        // FFd/2 words

// ---------------- scratch (static device globals; no runtime alloc) ----------------
__device__ float    g_x[Nt*Hd];           // fp32 running activations
__device__ unsigned g_h[Nt*HW2];          // half2-packed LN output
__device__ unsigned g_qkv[Nt*QW2];        // half2-packed fused q|k|v
__device__ unsigned g_ctx[Nt*HW2];        // half2-packed attention output
__device__ unsigned g_ff[Nt*FW2];         // half2-packed FFN hidden
// prepacked fp16 weights: [K/2 words][N], word = half2(W[2k][n], W[2k+1][n])
__device__ unsigned g_wqkv[Lx*HW2*QKVW];
__device__ unsigned g_wo[Lx*HW2*Hd];
__device__ unsigned g_w1[Lx*HW2*FFd];
__device__ unsigned g_w2[Lx*FW2*Hd];
__device__ unsigned g_wg[HW2*Vocab];
__device__ float    g_bqkv[Lx*QKVW];

// ---------------- helpers ----------------
__device__ __forceinline__ unsigned pack2(float a, float b) {
    __half2 h2 = __floats2half2_rn(a, b);   // .x = low = a
    return *reinterpret_cast<unsigned*>(&h2);
}

__device__ __forceinline__ void mma16(float* c,
                                      unsigned a0, unsigned a1, unsigned a2, unsigned a3,
                                      unsigned b0, unsigned b1) {
    asm volatile(
        "mma.sync.aligned.m16n8k16.row.col.f32.f16.f16.f32 "
        "{%0,%1,%2,%3}, {%4,%5,%6,%7}, {%8,%9}, {%0,%1,%2,%3};"
        : "+f"(c[0]), "+f"(c[1]), "+f"(c[2]), "+f"(c[3])
        : "r"(a0), "r"(a1), "r"(a2), "r"(a3), "r"(b0), "r"(b1));
}

__device__ __forceinline__ void cpa16(unsigned dst, const void* src) {
    asm volatile("cp.async.ca.shared.global [%0], [%1], 16;" :: "r"(dst), "l"(src));
}
__device__ __forceinline__ void cpa16p(unsigned dst, const void* src, int bytes) {
    asm volatile("cp.async.ca.shared.global [%0], [%1], 16, %2;" :: "r"(dst), "l"(src), "r"(bytes));
}
__device__ __forceinline__ void cp_commit() { asm volatile("cp.async.commit_group;"); }
template<int N> __device__ __forceinline__ void cp_wait() {
    asm volatile("cp.async.wait_group %0;" :: "n"(N));
}

// ---------------- weight prepack (vectorized): fp32 [rows][N] -> half2 [rows/2][N] ----------------
__global__ void conv_pack(const float* __restrict__ src,
                          unsigned* __restrict__ dst, int N, int totalWords)
{
    int N4 = N >> 2;
    int totalQ = totalWords >> 2;
    for (int q = blockIdx.x * blockDim.x + threadIdx.x;
         q < totalQ; q += gridDim.x * blockDim.x) {
        int r2 = q / N4, n4 = q - r2 * N4;
        const float4 a = *(const float4*)&src[(size_t)(2*r2)*N + n4*4];
        const float4 c = *(const float4*)&src[(size_t)(2*r2+1)*N + n4*4];
        uint4 w;
        w.x = pack2(a.x, c.x);
        w.y = pack2(a.y, c.y);
        w.z = pack2(a.z, c.z);
        w.w = pack2(a.w, c.w);
        *(uint4*)&dst[(size_t)q*4] = w;
    }
}

__global__ void pack_qkv_kernel(const float* __restrict__ Wq,
                                const float* __restrict__ Wk,
                                const float* __restrict__ Wv,
                                unsigned* __restrict__ dst)
{
    const int N4 = QKVW >> 2;
    int totalQ = Lx*HW2*N4;
    for (int q = blockIdx.x * blockDim.x + threadIdx.x;
         q < totalQ; q += gridDim.x * blockDim.x) {
        int l = q / (HW2*N4);
        int rem = q - l * HW2*N4;
        int k2 = rem / N4;
        int n = (rem - k2 * N4) * 4;
        const float* Wm; int nn;
        if (n < Hd)        { Wm = Wq; nn = n; }
        else if (n < 2*Hd) { Wm = Wk; nn = n - Hd; }
        else               { Wm = Wv; nn = n - 2*Hd; }
        const float4 a = *(const float4*)&Wm[(size_t)l*Hd*Hd + (size_t)(2*k2)*Hd + nn];
        const float4 c = *(const float4*)&Wm[(size_t)l*Hd*Hd + (size_t)(2*k2+1)*Hd + nn];
        uint4 w;
        w.x = pack2(a.x, c.x);
        w.y = pack2(a.y, c.y);
        w.z = pack2(a.z, c.z);
        w.w = pack2(a.w, c.w);
        *(uint4*)&dst[((size_t)l*HW2 + k2)*QKVW + n] = w;
    }
}

__global__ void pack_bqkv_kernel(const float* __restrict__ bq,
                                 const float* __restrict__ bk,
                                 const float* __restrict__ bv,
                                 float* __restrict__ dst)
{
    int idx = blockIdx.x * blockDim.x + threadIdx.x;
    if (idx >= Lx*QKVW) return;
    int l = idx / QKVW;
    int n = idx - l * QKVW;
    float val;
    if (n < Hd)        val = bq[l*Hd + n];
    else if (n < 2*Hd) val = bk[l*Hd + (n - Hd)];
    else               val = bv[l*Hd + (n - 2*Hd)];
    dst[idx] = val;
}

// ---------------- embedding + sinusoidal positional encoding ----------------
__global__ void embed_kernel(const int* __restrict__ src,
                             const float* __restrict__ emb,
                             float* __restrict__ x)
{
    int idx = blockIdx.x * blockDim.x + threadIdx.x;
    if (idx >= Nt*Hd) return;
    int n = idx >> 9;
    int c = idx & (Hd-1);
    int s = n & (Sd-1);
    int tok = src[n];
    int i2 = c & ~1;
    float div = expf(-(logf(10000.0f)/(float)Hd) * (float)i2);
    float ang = (float)s * div;
    float pe = (c & 1) ? cosf(ang) : sinf(ang);
    x[idx] = emb[(size_t)tok*Hd + c] + pe;
}

// ---------------- layernorm: warp per row, no block sync. fp32 in -> half2 out ----------------
__global__ void layernorm_kernel(const float* __restrict__ x,
                                 const float* __restrict__ g,
                                 const float* __restrict__ b,
                                 unsigned* __restrict__ out)
{
    int wid = threadIdx.x >> 5, lane = threadIdx.x & 31;
    int row = blockIdx.x * 8 + wid;
    const float* xr = x + (size_t)row*Hd;

    float4 v[4];
    #pragma unroll
    for (int ch = 0; ch < 4; ch++)
        v[ch] = *(const float4*)(xr + ch*128 + lane*4);

    float s = 0.f;
    #pragma unroll
    for (int ch = 0; ch < 4; ch++) s += v[ch].x + v[ch].y + v[ch].z + v[ch].w;
    #pragma unroll
    for (int o = 16; o > 0; o >>= 1) s += __shfl_xor_sync(0xffffffffu, s, o);
    float mean = s * (1.0f/(float)Hd);

    float ss = 0.f;
    #pragma unroll
    for (int ch = 0; ch < 4; ch++) {
        float dx = v[ch].x - mean, dy = v[ch].y - mean;
        float dz = v[ch].z - mean, dw = v[ch].w - mean;
        ss += dx*dx + dy*dy + dz*dz + dw*dw;
    }
    #pragma unroll
    for (int o = 16; o > 0; o >>= 1) ss += __shfl_xor_sync(0xffffffffu, ss, o);
    float rstd = rsqrtf(ss * (1.0f/(float)Hd) + 1e-5f);

    #pragma unroll
    for (int ch = 0; ch < 4; ch++) {
        int c = ch*128 + lane*4;
        float4 gg = *(const float4*)(g + c);
        float4 bb = *(const float4*)(b + c);
        float o0 = (v[ch].x - mean)*rstd*gg.x + bb.x;
        float o1 = (v[ch].y - mean)*rstd*gg.y + bb.y;
        float o2 = (v[ch].z - mean)*rstd*gg.z + bb.z;
        float o3 = (v[ch].w - mean)*rstd*gg.w + bb.w;
        uint2 w2 = make_uint2(pack2(o0, o1), pack2(o2, o3));
        *(uint2*)(out + (size_t)row*HW2 + (c >> 1)) = w2;
    }
}

// ============================================================================
// fp16 GEMM: 3-stage compute-then-prefetch (R13 schedule), 64-k stages
// (GKTW=32 words) -> half the barriers, 4 k16 chunks of ILP per stage.
// A [M][K2] half2 words (k-pairs), B [K2][N] half2 words.
// OUT modes: 0 = f32 + residual, 2 = half2+relu,
//            3 = half2 with cols<Hd scaled 0.125 (fused QKV), 4 = f32 plain
// ============================================================================
#define GKTW 32     // k-words per stage (64 k)
#define APAD 36
#define BPAD 136
#define GEMM_SMEM ((3*128*APAD + 3*GKTW*BPAD) * 4)

template<int OM>
__global__ void __launch_bounds__(256, 2)
gemm_hk(const unsigned* __restrict__ A,
        const unsigned* __restrict__ B,
        const float* __restrict__ bias,
        const float* __restrict__ R,
        void* __restrict__ Cv,
        int M, int N, int K2)
{
    extern __shared__ unsigned gsm[];
    unsigned* As = gsm;                 // [3][128][APAD]
    unsigned* Bs = gsm + 3*128*APAD;    // [3][GKTW][BPAD]

    int tid = threadIdx.x;
    int wid = tid >> 5, lane = tid & 31;
    int g = lane >> 2, t = lane & 3;
    int wm = (wid >> 2) * 64;
    int wn = (wid & 3) * 32;
    int rowBase = blockIdx.y * 128;
    int colBase = blockIdx.x * 128;

    float acc[4][4][4];
    #pragma unroll
    for (int mi = 0; mi < 4; mi++)
        #pragma unroll
        for (int ni = 0; ni < 4; ni++)
            #pragma unroll
            for (int r = 0; r < 4; r++) acc[mi][ni][r] = 0.0f;

    int nst = K2 / GKTW;

    auto loadStage = [&](int st, int k0w) {
        unsigned* Adst = As + st*128*APAD;
        unsigned* Bdst = Bs + st*GKTW*BPAD;
        #pragma unroll
        for (int i = 0; i < 4; i++) {
            int li = tid + i * 256;
            int r = li >> 3, kq = (li & 7) * 4;
            cpa16((unsigned)__cvta_generic_to_shared(&Adst[r*APAD + kq]),
                  &A[(size_t)(rowBase + r) * K2 + k0w + kq]);
        }
        #pragma unroll
        for (int i = 0; i < 4; i++) {
            int li = tid + i * 256;
            int r = li >> 5, cq = (li & 31) * 4;
            int gc = colBase + cq;
            cpa16p((unsigned)__cvta_generic_to_shared(&Bdst[r*BPAD + cq]),
                   &B[(size_t)(k0w + r) * N + gc], (gc + 4 <= N) ? 16 : 0);
        }
        cp_commit();
    };

    auto computeStage = [&](int st) {
        const unsigned* Asrc = As + st*128*APAD;
        const unsigned* Bsrc = Bs + st*GKTW*BPAD;
        #pragma unroll
        for (int kk2 = 0; kk2 < GKTW; kk2 += 8) {   // 4 x k16 chunks
            unsigned a[4][4], b[4][2];
            #pragma unroll
            for (int mi = 0; mi < 4; mi++) {
                int m = wm + mi * 16 + g;
                a[mi][0] = Asrc[m*APAD       + kk2 + t];
                a[mi][1] = Asrc[(m + 8)*APAD + kk2 + t];
                a[mi][2] = Asrc[m*APAD       + kk2 + 4 + t];
                a[mi][3] = Asrc[(m + 8)*APAD + kk2 + 4 + t];
            }
            #pragma unroll
            for (int ni = 0; ni < 4; ni++) {
                int n = wn + ni * 8 + g;
                b[ni][0] = Bsrc[(kk2 + t)*BPAD     + n];
                b[ni][1] = Bsrc[(kk2 + 4 + t)*BPAD + n];
            }
            #pragma unroll
            for (int mi = 0; mi < 4; mi++)
                #pragma unroll
                for (int ni = 0; ni < 4; ni++)
                    mma16(acc[mi][ni], a[mi][0], a[mi][1], a[mi][2], a[mi][3],
                          b[ni][0], b[ni][1]);
        }
    };

    loadStage(0, 0);
    if (nst > 1) loadStage(1, GKTW);

    for (int s = 0; s < nst; s++) {
        if (s + 1 < nst) cp_wait<1>(); else cp_wait<0>();
        __syncthreads();
        computeStage(s % 3);
        if (s + 2 < nst) loadStage((s + 2) % 3, (s + 2) * GKTW);
    }

    #pragma unroll
    for (int mi = 0; mi < 4; mi++) {
        #pragma unroll
        for (int ni = 0; ni < 4; ni++) {
            int r0 = rowBase + wm + mi * 16 + g;
            int c0 = colBase + wn + ni * 8 + 2 * t;   // even
            if (c0 < N) {
                float bx = bias[c0], by = bias[c0 + 1];
                float v00 = acc[mi][ni][0] + bx;
                float v01 = acc[mi][ni][1] + by;
                float v10 = acc[mi][ni][2] + bx;
                float v11 = acc[mi][ni][3] + by;
                if (OM == 0) {
                    float* C = (float*)Cv;
                    float2 ra = *(const float2*)&R[(size_t)r0 * N + c0];
                    float2 rb = *(const float2*)&R[(size_t)(r0 + 8) * N + c0];
                    *(float2*)&C[(size_t)r0 * N + c0]       = make_float2(v00 + ra.x, v01 + ra.y);
                    *(float2*)&C[(size_t)(r0 + 8) * N + c0] = make_float2(v10 + rb.x, v11 + rb.y);
                } else if (OM == 4) {
                    float* C = (float*)Cv;
                    *(float2*)&C[(size_t)r0 * N + c0]       = make_float2(v00, v01);
                    *(float2*)&C[(size_t)(r0 + 8) * N + c0] = make_float2(v10, v11);
                } else {
                    if (OM == 2) {
                        v00 = fmaxf(v00, 0.f); v01 = fmaxf(v01, 0.f);
                        v10 = fmaxf(v10, 0.f); v11 = fmaxf(v11, 0.f);
                    }
                    if (OM == 3 && c0 < Hd) {
                        v00 *= 0.125f; v01 *= 0.125f;
                        v10 *= 0.125f; v11 *= 0.125f;
                    }
                    unsigned* C = (unsigned*)Cv;
                    int n2 = N >> 1;
                    C[(size_t)r0 * n2 + (c0 >> 1)]       = pack2(v00, v01);
                    C[(size_t)(r0 + 8) * n2 + (c0 >> 1)] = pack2(v10, v11);
                }
            }
        }
    }
}

// ============================================================================
// fp16 flash attention (R13: 3-buffer ring, 1 sync/tile, register P,
// direct V gather via byte_perm)
// ============================================================================
#define KPAD 36
#define VPAD 36
#define FLASH_SMEM ((3*128*KPAD + 3*128*VPAD) * 4 + 512)

__global__ void __launch_bounds__(256, 1)
flash_attn(const unsigned* __restrict__ qkv,
           const unsigned char* __restrict__ mask,
           unsigned* __restrict__ ctx)
{
    extern __shared__ unsigned fsm[];
    unsigned* Ks = fsm;                         // [3][128][KPAD]
    unsigned* Vs = Ks + 3*128*KPAD;             // [3][128][VPAD]
    unsigned char* Ms = (unsigned char*)(Vs + 3*128*VPAD);   // 3*128

    int bi = blockIdx.y;
    int b = bi >> 3, h = bi & 7;
    int qBase = blockIdx.x * 128;
    const unsigned* Qg = qkv + (size_t)b*Sd*QW2 + h*(DKd/2);
    const unsigned* Kg = qkv + (size_t)b*Sd*QW2 + HW2     + h*(DKd/2);
    const unsigned* Vg = qkv + (size_t)b*Sd*QW2 + 2*HW2   + h*(DKd/2);
    const unsigned char* mr = mask + (size_t)b*Sd;
    unsigned* Cg = ctx + (size_t)b*Sd*HW2 + h*(DKd/2);

    int tid = threadIdx.x;
    int wid = tid >> 5, lane = tid & 31;
    int g = lane >> 2, t = lane & 3;
    int wm = wid * 16;

    unsigned qf[4][4];
    {
        int r0 = qBase + wm + g, r1 = r0 + 8;
        #pragma unroll
        for (int c = 0; c < 4; c++) {
            qf[c][0] = Qg[(size_t)r0*QW2 + c*8 + t];
            qf[c][1] = Qg[(size_t)r1*QW2 + c*8 + t];
            qf[c][2] = Qg[(size_t)r0*QW2 + c*8 + 4 + t];
            qf[c][3] = Qg[(size_t)r1*QW2 + c*8 + 4 + t];
        }
    }

    float m0 = -1e30f, m1 = -1e30f, l0 = 0.f, l1 = 0.f;
    float o[8][4];
    #pragma unroll
    for (int i = 0; i < 8; i++)
        #pragma unroll
        for (int r = 0; r < 4; r++) o[i][r] = 0.f;

    auto loadTile = [&](int kt, int buf) {
        unsigned* Ktile = Ks + buf*128*KPAD;
        unsigned* Vtile = Vs + buf*128*VPAD;
        #pragma unroll
        for (int i = 0; i < 4; i++) {
            int li = tid + i * 256;
            int r = li >> 3, cq = (li & 7) * 4;
            cpa16((unsigned)__cvta_generic_to_shared(&Ktile[r*KPAD + cq]),
                  &Kg[(size_t)(kt*128 + r)*QW2 + cq]);
            cpa16((unsigned)__cvta_generic_to_shared(&Vtile[r*VPAD + cq]),
                  &Vg[(size_t)(kt*128 + r)*QW2 + cq]);
        }
        if (tid < 32) {
            uchar4 mv = *(const uchar4*)&mr[kt*128 + tid*4];
            *(uchar4*)&Ms[buf*128 + tid*4] = mv;
        }
        cp_commit();
    };

    const int NT = Sd / 128;   // 16
    loadTile(0, 0);

    for (int kt = 0; kt < NT; kt++) {
        int buf = kt % 3;
        if (kt + 1 < NT) { loadTile(kt + 1, (kt + 1) % 3); cp_wait<1>(); }
        else             { cp_wait<0>(); }
        __syncthreads();   // tile kt visible; bounds warp drift to 1 iter

        const unsigned* Ktile = Ks + buf*128*KPAD;
        const unsigned* Vtile = Vs + buf*128*VPAD;
        const unsigned char* Mt = Ms + buf*128;

        // ---- S = Q K^T ----
        float s[16][4];
        #pragma unroll
        for (int ni = 0; ni < 16; ni++)
            #pragma unroll
            for (int r = 0; r < 4; r++) s[ni][r] = 0.f;

        #pragma unroll
        for (int c = 0; c < 4; c++) {
            #pragma unroll
            for (int ni = 0; ni < 16; ni++) {
                int n = ni*8 + g;
                unsigned b0 = Ktile[n*KPAD + c*8 + t];
                unsigned b1 = Ktile[n*KPAD + c*8 + 4 + t];
                mma16(s[ni], qf[c][0], qf[c][1], qf[c][2], qf[c][3], b0, b1);
            }
        }

        // ---- mask + row max ----
        float mt0 = -1e30f, mt1 = -1e30f;
        #pragma unroll
        for (int ni = 0; ni < 16; ni++) {
            int c = ni*8 + 2*t;
            if (Mt[c])     { s[ni][0] = -1e30f; s[ni][2] = -1e30f; }
            if (Mt[c + 1]) { s[ni][1] = -1e30f; s[ni][3] = -1e30f; }
            mt0 = fmaxf(mt0, fmaxf(s[ni][0], s[ni][1]));
            mt1 = fmaxf(mt1, fmaxf(s[ni][2], s[ni][3]));
        }
        mt0 = fmaxf(mt0, __shfl_xor_sync(0xffffffffu, mt0, 1));
        mt0 = fmaxf(mt0, __shfl_xor_sync(0xffffffffu, mt0, 2));
        mt1 = fmaxf(mt1, __shfl_xor_sync(0xffffffffu, mt1, 1));
        mt1 = fmaxf(mt1, __shfl_xor_sync(0xffffffffu, mt1, 2));

        float mn0 = fmaxf(m0, mt0), mn1 = fmaxf(m1, mt1);
        float c0s = __expf(m0 - mn0), c1s = __expf(m1 - mn1);
        m0 = mn0; m1 = mn1;

        // ---- exp in-place + row sums ----
        float rs0 = 0.f, rs1 = 0.f;
        #pragma unroll
        for (int ni = 0; ni < 16; ni++) {
            s[ni][0] = __expf(s[ni][0] - m0);
            s[ni][1] = __expf(s[ni][1] - m0);
            s[ni][2] = __expf(s[ni][2] - m1);
            s[ni][3] = __expf(s[ni][3] - m1);
            rs0 += s[ni][0] + s[ni][1];
            rs1 += s[ni][2] + s[ni][3];
        }
        rs0 += __shfl_xor_sync(0xffffffffu, rs0, 1);
        rs0 += __shfl_xor_sync(0xffffffffu, rs0, 2);
        rs1 += __shfl_xor_sync(0xffffffffu, rs1, 1);
        rs1 += __shfl_xor_sync(0xffffffffu, rs1, 2);
        l0 = l0 * c0s + rs0;
        l1 = l1 * c1s + rs1;

        #pragma unroll
        for (int oni = 0; oni < 8; oni++) {
            o[oni][0] *= c0s; o[oni][1] *= c0s;
            o[oni][2] *= c1s; o[oni][3] *= c1s;
        }

        // ---- O += P V ----
        {
            unsigned sel = (g & 1) ? 0x7632u : 0x5410u;
            #pragma unroll
            for (int kk = 0; kk < 8; kk++) {
                unsigned a0 = pack2(s[2*kk][0],   s[2*kk][1]);
                unsigned a1 = pack2(s[2*kk][2],   s[2*kk][3]);
                unsigned a2 = pack2(s[2*kk+1][0], s[2*kk+1][1]);
                unsigned a3 = pack2(s[2*kk+1][2], s[2*kk+1][3]);
                const unsigned* V0a = Vtile + (2*(kk*8 + t))*VPAD;
                const unsigned* V0b = V0a + VPAD;
                const unsigned* V1a = Vtile + (2*(kk*8 + 4 + t))*VPAD;
                const unsigned* V1b = V1a + VPAD;
                #pragma unroll
                for (int oni = 0; oni < 8; oni++) {
                    int dw = oni*4 + (g >> 1);
                    unsigned b0 = __byte_perm(V0a[dw], V0b[dw], sel);
                    unsigned b1 = __byte_perm(V1a[dw], V1b[dw], sel);
                    mma16(o[oni], a0, a1, a2, a3, b0, b1);
                }
            }
        }
    }

    // ---- epilogue ----
    float i0 = 1.f / l0, i1 = 1.f / l1;
    int r0 = qBase + wm + g, r1 = r0 + 8;
    #pragma unroll
    for (int oni = 0; oni < 8; oni++) {
        int wrd = oni*4 + t;
        Cg[(size_t)r0*HW2 + wrd] = pack2(o[oni][0] * i0, o[oni][1] * i0);
        Cg[(size_t)r1*HW2 + wrd] = pack2(o[oni][2] * i1, o[oni][3] * i1);
    }
}

// ---------------- launch ----------------
extern "C" void kernel_launch(void* const* d_in, const int* in_sizes, int n_in,
                              void* d_out, int out_size)
{
    const int*           src  = (const int*)d_in[0];
    const unsigned char* mask = (const unsigned char*)d_in[1];
    const float* emb  = (const float*)d_in[2];
    const float* Wq   = (const float*)d_in[3];
    const float* bq   = (const float*)d_in[4];
    const float* Wk   = (const float*)d_in[5];
    const float* bk   = (const float*)d_in[6];
    const float* Wv   = (const float*)d_in[7];
    const float* bv   = (const float*)d_in[8];
    const float* Wo   = (const float*)d_in[9];
    const float* bo   = (const float*)d_in[10];
    const float* ln1g = (const float*)d_in[11];
    const float* ln1b = (const float*)d_in[12];
    const float* W1   = (const float*)d_in[13];
    const float* b1   = (const float*)d_in[14];
    const float* W2   = (const float*)d_in[15];
    const float* b2   = (const float*)d_in[16];
    const float* ln2g = (const float*)d_in[17];
    const float* ln2b = (const float*)d_in[18];
    const float* lnfg = (const float*)d_in[19];
    const float* lnfb = (const float*)d_in[20];
    const float* Wg   = (const float*)d_in[21];
    const float* bg   = (const float*)d_in[22];
    float* out = (float*)d_out;

    float *x;   unsigned *h, *qkv, *ctx, *ff;
    unsigned *wqkv, *wo, *w1, *w2, *wg;  float *bqkv;
    cudaGetSymbolAddress((void**)&x,    g_x);
    cudaGetSymbolAddress((void**)&h,    g_h);
    cudaGetSymbolAddress((void**)&qkv,  g_qkv);
    cudaGetSymbolAddress((void**)&ctx,  g_ctx);
    cudaGetSymbolAddress((void**)&ff,   g_ff);
    cudaGetSymbolAddress((void**)&wqkv, g_wqkv);
    cudaGetSymbolAddress((void**)&wo,   g_wo);
    cudaGetSymbolAddress((void**)&w1,   g_w1);
    cudaGetSymbolAddress((void**)&w2,   g_w2);
    cudaGetSymbolAddress((void**)&wg,   g_wg);
    cudaGetSymbolAddress((void**)&bqkv, g_bqkv);

    static bool attr_set = false;
    if (!attr_set) {
        cudaFuncSetAttribute(flash_attn,
                             cudaFuncAttributeMaxDynamicSharedMemorySize, FLASH_SMEM);
        cudaFuncSetAttribute(gemm_hk<0>,
                             cudaFuncAttributeMaxDynamicSharedMemorySize, GEMM_SMEM);
        cudaFuncSetAttribute(gemm_hk<2>,
                             cudaFuncAttributeMaxDynamicSharedMemorySize, GEMM_SMEM);
        cudaFuncSetAttribute(gemm_hk<3>,
                             cudaFuncAttributeMaxDynamicSharedMemorySize, GEMM_SMEM);
        cudaFuncSetAttribute(gemm_hk<4>,
                             cudaFuncAttributeMaxDynamicSharedMemorySize, GEMM_SMEM);
        attr_set = true;
    }

    // ---- prepack weights to half2 words ----
    pack_qkv_kernel<<<1184, 256>>>(Wq, Wk, Wv, wqkv);
    pack_bqkv_kernel<<<(Lx*QKVW + 255)/256, 256>>>(bq, bk, bv, bqkv);
    conv_pack<<<1184, 256>>>(Wo, wo, Hd,    Lx*HW2*Hd);
    conv_pack<<<1184, 256>>>(W1, w1, FFd,   Lx*HW2*FFd);
    conv_pack<<<1184, 256>>>(W2, w2, Hd,    Lx*FW2*Hd);
    conv_pack<<<1184, 256>>>(Wg, wg, Vocab, HW2*Vocab);

    embed_kernel<<<(Nt*Hd + 255)/256, 256>>>(src, emb, x);

    dim3 gQKV(QKVW/128, Nt/128);
    dim3 gH(Hd/128,  Nt/128);
    dim3 gF(FFd/128, Nt/128);
    dim3 gV((Vocab+127)/128, Nt/128);

    for (int l = 0; l < Lx; l++) {
        layernorm_kernel<<<Nt/8, 256>>>(x, ln1g + (size_t)l*Hd, ln1b + (size_t)l*Hd, h);

        // fused QKV (q cols pre-scaled by 1/8, half2 out)
        gemm_hk<3><<<gQKV, 256, GEMM_SMEM>>>(h, wqkv + (size_t)l*HW2*QKVW, bqkv + (size_t)l*QKVW,
                                             nullptr, qkv, Nt, QKVW, HW2);

        flash_attn<<<dim3(Sd/128, Bd*NHd), 256, FLASH_SMEM>>>(qkv, mask, ctx);

        // x = x + ctx @ Wo + bo
        gemm_hk<0><<<gH, 256, GEMM_SMEM>>>(ctx, wo + (size_t)l*HW2*Hd, bo + (size_t)l*Hd,
                                           x, x, Nt, Hd, HW2);

        layernorm_kernel<<<Nt/8, 256>>>(x, ln2g + (size_t)l*Hd, ln2b + (size_t)l*Hd, h);

        // ff = relu(h @ W1 + b1) (half2 out)
        gemm_hk<2><<<gF, 256, GEMM_SMEM>>>(h, w1 + (size_t)l*HW2*FFd, b1 + (size_t)l*FFd,
                                           nullptr, ff, Nt, FFd, HW2);
        // x = x + ff @ W2 + b2
        gemm_hk<0><<<gH, 256, GEMM_SMEM>>>(ff, w2 + (size_t)l*FW2*Hd, b2 + (size_t)l*Hd,
                                           x, x, Nt, Hd, FW2);
    }

    layernorm_kernel<<<Nt/8, 256>>>(x, lnfg, lnfb, h);
    gemm_hk<4><<<gV, 256, GEMM_SMEM>>>(h, wg, bg, nullptr, out, Nt, Vocab, HW2);
}

// round 17
// speedup vs baseline: 1.0590x; 1.0042x over previous
#include <cuda_runtime.h>
#include <cuda_fp16.h>
#include <math.h>

// Problem constants
#define Lx  6
#define Hd  512
#define NHd 8
#define FFd 2048
#define Vocab 10000
#define Bd  4
#define Sd  2048
#define DKd 64
#define Nt  (Bd*Sd)     // 8192 tokens
#define QKVW 1536       // fused QKV width
#define QW2 768         // QKVW/2 words
#define HW2 256         // Hd/2 words
#define FW2 1024        // FFd/2 words

// ---------------- scratch (static device globals; no runtime alloc) ----------------
__device__ float    g_x[Nt*Hd];           // fp32 running activations
__device__ unsigned g_h[Nt*HW2];          // half2-packed LN output
__device__ unsigned g_qkv[Nt*QW2];        // half2-packed fused q|k|v
__device__ unsigned g_ctx[Nt*HW2];        // half2-packed attention output
__device__ unsigned g_ff[Nt*FW2];         // half2-packed FFN hidden
// prepacked fp16 weights: [K/2 words][N], word = half2(W[2k][n], W[2k+1][n])
__device__ unsigned g_wqkv[Lx*HW2*QKVW];
__device__ unsigned g_wo[Lx*HW2*Hd];
__device__ unsigned g_w1[Lx*HW2*FFd];
__device__ unsigned g_w2[Lx*FW2*Hd];
__device__ unsigned g_wg[HW2*Vocab];
__device__ float    g_bqkv[Lx*QKVW];

// ---------------- helpers ----------------
__device__ __forceinline__ unsigned pack2(float a, float b) {
    __half2 h2 = __floats2half2_rn(a, b);   // .x = low = a
    return *reinterpret_cast<unsigned*>(&h2);
}

__device__ __forceinline__ void mma16(float* c,
                                      unsigned a0, unsigned a1, unsigned a2, unsigned a3,
                                      unsigned b0, unsigned b1) {
    asm volatile(
        "mma.sync.aligned.m16n8k16.row.col.f32.f16.f16.f32 "
        "{%0,%1,%2,%3}, {%4,%5,%6,%7}, {%8,%9}, {%0,%1,%2,%3};"
        : "+f"(c[0]), "+f"(c[1]), "+f"(c[2]), "+f"(c[3])
        : "r"(a0), "r"(a1), "r"(a2), "r"(a3), "r"(b0), "r"(b1));
}

__device__ __forceinline__ void cpa16(unsigned dst, const void* src) {
    asm volatile("cp.async.ca.shared.global [%0], [%1], 16;" :: "r"(dst), "l"(src));
}
__device__ __forceinline__ void cpa16p(unsigned dst, const void* src, int bytes) {
    asm volatile("cp.async.ca.shared.global [%0], [%1], 16, %2;" :: "r"(dst), "l"(src), "r"(bytes));
}
__device__ __forceinline__ void cp_commit() { asm volatile("cp.async.commit_group;"); }
template<int N> __device__ __forceinline__ void cp_wait() {
    asm volatile("cp.async.wait_group %0;" :: "n"(N));
}

// ---------------- combined weight prepack: 4 segments in ONE launch ----------------
// fp32 [rows][N] -> half2 [rows/2][N], vectorized (quads of words)
__device__ __forceinline__ void pack_quads(const float* __restrict__ src,
                                           unsigned* __restrict__ dst,
                                           int N, int qStart, int qEnd,
                                           int stride, int base)
{
    int N4 = N >> 2;
    for (int q = base + qStart; q < qEnd; q += stride) {
        int ql = q - qStart;
        int r2 = ql / N4, n4 = ql - r2 * N4;
        const float4 a = *(const float4*)&src[(size_t)(2*r2)*N + n4*4];
        const float4 c = *(const float4*)&src[(size_t)(2*r2+1)*N + n4*4];
        uint4 w;
        w.x = pack2(a.x, c.x);
        w.y = pack2(a.y, c.y);
        w.z = pack2(a.z, c.z);
        w.w = pack2(a.w, c.w);
        *(uint4*)&dst[(size_t)ql*4] = w;
    }
}

#define QWO (Lx*HW2*Hd/4)     // 196608
#define QW1 (Lx*HW2*FFd/4)    // 786432
#define QW2Q (Lx*FW2*Hd/4)    // 786432
#define QWG (HW2*Vocab/4)     // 640000

__global__ void conv_pack_all(const float* __restrict__ Wo,  unsigned* __restrict__ wo,
                              const float* __restrict__ W1,  unsigned* __restrict__ w1,
                              const float* __restrict__ W2,  unsigned* __restrict__ w2,
                              const float* __restrict__ Wg,  unsigned* __restrict__ wg)
{
    int stride = gridDim.x * blockDim.x;
    int base = blockIdx.x * blockDim.x + threadIdx.x;
    // segment boundaries (in quads)
    const int e0 = QWO;
    const int e1 = e0 + QW1;
    const int e2 = e1 + QW2Q;
    const int e3 = e2 + QWG;
    // each thread strides the full range; dispatch per segment keeps the
    // vectorized body branch-uniform at warp granularity except at edges
    pack_quads(Wo, wo, Hd,    0,  e0, stride, base);
    pack_quads(W1, w1, FFd,   e0, e1, stride, base);
    pack_quads(W2, w2, Hd,    e1, e2, stride, base);
    pack_quads(Wg, wg, Vocab, e2, e3, stride, base);
}

__global__ void pack_qkv_kernel(const float* __restrict__ Wq,
                                const float* __restrict__ Wk,
                                const float* __restrict__ Wv,
                                unsigned* __restrict__ dst)
{
    const int N4 = QKVW >> 2;
    int totalQ = Lx*HW2*N4;
    for (int q = blockIdx.x * blockDim.x + threadIdx.x;
         q < totalQ; q += gridDim.x * blockDim.x) {
        int l = q / (HW2*N4);
        int rem = q - l * HW2*N4;
        int k2 = rem / N4;
        int n = (rem - k2 * N4) * 4;
        const float* Wm; int nn;
        if (n < Hd)        { Wm = Wq; nn = n; }
        else if (n < 2*Hd) { Wm = Wk; nn = n - Hd; }
        else               { Wm = Wv; nn = n - 2*Hd; }
        const float4 a = *(const float4*)&Wm[(size_t)l*Hd*Hd + (size_t)(2*k2)*Hd + nn];
        const float4 c = *(const float4*)&Wm[(size_t)l*Hd*Hd + (size_t)(2*k2+1)*Hd + nn];
        uint4 w;
        w.x = pack2(a.x, c.x);
        w.y = pack2(a.y, c.y);
        w.z = pack2(a.z, c.z);
        w.w = pack2(a.w, c.w);
        *(uint4*)&dst[((size_t)l*HW2 + k2)*QKVW + n] = w;
    }
}

__global__ void pack_bqkv_kernel(const float* __restrict__ bq,
                                 const float* __restrict__ bk,
                                 const float* __restrict__ bv,
                                 float* __restrict__ dst)
{
    int idx = blockIdx.x * blockDim.x + threadIdx.x;
    if (idx >= Lx*QKVW) return;
    int l = idx / QKVW;
    int n = idx - l * QKVW;
    float val;
    if (n < Hd)        val = bq[l*Hd + n];
    else if (n < 2*Hd) val = bk[l*Hd + (n - Hd)];
    else               val = bv[l*Hd + (n - 2*Hd)];
    dst[idx] = val;
}

// ---------------- embedding + sinusoidal positional encoding ----------------
__global__ void embed_kernel(const int* __restrict__ src,
                             const float* __restrict__ emb,
                             float* __restrict__ x)
{
    int idx = blockIdx.x * blockDim.x + threadIdx.x;
    if (idx >= Nt*Hd) return;
    int n = idx >> 9;
    int c = idx & (Hd-1);
    int s = n & (Sd-1);
    int tok = src[n];
    int i2 = c & ~1;
    float div = expf(-(logf(10000.0f)/(float)Hd) * (float)i2);
    float ang = (float)s * div;
    float pe = (c & 1) ? cosf(ang) : sinf(ang);
    x[idx] = emb[(size_t)tok*Hd + c] + pe;
}

// ---------------- layernorm: warp per row, no block sync. fp32 in -> half2 out ----------------
__global__ void layernorm_kernel(const float* __restrict__ x,
                                 const float* __restrict__ g,
                                 const float* __restrict__ b,
                                 unsigned* __restrict__ out)
{
    int wid = threadIdx.x >> 5, lane = threadIdx.x & 31;
    int row = blockIdx.x * 8 + wid;
    const float* xr = x + (size_t)row*Hd;

    float4 v[4];
    #pragma unroll
    for (int ch = 0; ch < 4; ch++)
        v[ch] = *(const float4*)(xr + ch*128 + lane*4);

    float s = 0.f;
    #pragma unroll
    for (int ch = 0; ch < 4; ch++) s += v[ch].x + v[ch].y + v[ch].z + v[ch].w;
    #pragma unroll
    for (int o = 16; o > 0; o >>= 1) s += __shfl_xor_sync(0xffffffffu, s, o);
    float mean = s * (1.0f/(float)Hd);

    float ss = 0.f;
    #pragma unroll
    for (int ch = 0; ch < 4; ch++) {
        float dx = v[ch].x - mean, dy = v[ch].y - mean;
        float dz = v[ch].z - mean, dw = v[ch].w - mean;
        ss += dx*dx + dy*dy + dz*dz + dw*dw;
    }
    #pragma unroll
    for (int o = 16; o > 0; o >>= 1) ss += __shfl_xor_sync(0xffffffffu, ss, o);
    float rstd = rsqrtf(ss * (1.0f/(float)Hd) + 1e-5f);

    #pragma unroll
    for (int ch = 0; ch < 4; ch++) {
        int c = ch*128 + lane*4;
        float4 gg = *(const float4*)(g + c);
        float4 bb = *(const float4*)(b + c);
        float o0 = (v[ch].x - mean)*rstd*gg.x + bb.x;
        float o1 = (v[ch].y - mean)*rstd*gg.y + bb.y;
        float o2 = (v[ch].z - mean)*rstd*gg.z + bb.z;
        float o3 = (v[ch].w - mean)*rstd*gg.w + bb.w;
        uint2 w2 = make_uint2(pack2(o0, o1), pack2(o2, o3));
        *(uint2*)(out + (size_t)row*HW2 + (c >> 1)) = w2;
    }
}

// ============================================================================
// fp16 GEMM: 3-stage compute-then-prefetch, 64-k stages (GKTW=32 words).
// A [M][K2] half2 words (k-pairs), B [K2][N] half2 words.
// OUT modes: 0 = f32 + residual, 2 = half2+relu,
//            3 = half2 with cols<Hd scaled 0.125 (fused QKV), 4 = f32 plain
// ============================================================================
#define GKTW 32     // k-words per stage (64 k)
#define APAD 36
#define BPAD 136
#define GEMM_SMEM ((3*128*APAD + 3*GKTW*BPAD) * 4)

template<int OM>
__global__ void __launch_bounds__(256, 2)
gemm_hk(const unsigned* __restrict__ A,
        const unsigned* __restrict__ B,
        const float* __restrict__ bias,
        const float* __restrict__ R,
        void* __restrict__ Cv,
        int M, int N, int K2)
{
    extern __shared__ unsigned gsm[];
    unsigned* As = gsm;                 // [3][128][APAD]
    unsigned* Bs = gsm + 3*128*APAD;    // [3][GKTW][BPAD]

    int tid = threadIdx.x;
    int wid = tid >> 5, lane = tid & 31;
    int g = lane >> 2, t = lane & 3;
    int wm = (wid >> 2) * 64;
    int wn = (wid & 3) * 32;
    int rowBase = blockIdx.y * 128;
    int colBase = blockIdx.x * 128;

    float acc[4][4][4];
    #pragma unroll
    for (int mi = 0; mi < 4; mi++)
        #pragma unroll
        for (int ni = 0; ni < 4; ni++)
            #pragma unroll
            for (int r = 0; r < 4; r++) acc[mi][ni][r] = 0.0f;

    int nst = K2 / GKTW;

    auto loadStage = [&](int st, int k0w) {
        unsigned* Adst = As + st*128*APAD;
        unsigned* Bdst = Bs + st*GKTW*BPAD;
        #pragma unroll
        for (int i = 0; i < 4; i++) {
            int li = tid + i * 256;
            int r = li >> 3, kq = (li & 7) * 4;
            cpa16((unsigned)__cvta_generic_to_shared(&Adst[r*APAD + kq]),
                  &A[(size_t)(rowBase + r) * K2 + k0w + kq]);
        }
        #pragma unroll
        for (int i = 0; i < 4; i++) {
            int li = tid + i * 256;
            int r = li >> 5, cq = (li & 31) * 4;
            int gc = colBase + cq;
            cpa16p((unsigned)__cvta_generic_to_shared(&Bdst[r*BPAD + cq]),
                   &B[(size_t)(k0w + r) * N + gc], (gc + 4 <= N) ? 16 : 0);
        }
        cp_commit();
    };

    auto computeStage = [&](int st) {
        const unsigned* Asrc = As + st*128*APAD;
        const unsigned* Bsrc = Bs + st*GKTW*BPAD;
        #pragma unroll
        for (int kk2 = 0; kk2 < GKTW; kk2 += 8) {   // 4 x k16 chunks
            unsigned a[4][4], b[4][2];
            #pragma unroll
            for (int mi = 0; mi < 4; mi++) {
                int m = wm + mi * 16 + g;
                a[mi][0] = Asrc[m*APAD       + kk2 + t];
                a[mi][1] = Asrc[(m + 8)*APAD + kk2 + t];
                a[mi][2] = Asrc[m*APAD       + kk2 + 4 + t];
                a[mi][3] = Asrc[(m + 8)*APAD + kk2 + 4 + t];
            }
            #pragma unroll
            for (int ni = 0; ni < 4; ni++) {
                int n = wn + ni * 8 + g;
                b[ni][0] = Bsrc[(kk2 + t)*BPAD     + n];
                b[ni][1] = Bsrc[(kk2 + 4 + t)*BPAD + n];
            }
            #pragma unroll
            for (int mi = 0; mi < 4; mi++)
                #pragma unroll
                for (int ni = 0; ni < 4; ni++)
                    mma16(acc[mi][ni], a[mi][0], a[mi][1], a[mi][2], a[mi][3],
                          b[ni][0], b[ni][1]);
        }
    };

    loadStage(0, 0);
    if (nst > 1) loadStage(1, GKTW);

    for (int s = 0; s < nst; s++) {
        if (s + 1 < nst) cp_wait<1>(); else cp_wait<0>();
        __syncthreads();
        computeStage(s % 3);
        if (s + 2 < nst) loadStage((s + 2) % 3, (s + 2) * GKTW);
    }

    #pragma unroll
    for (int mi = 0; mi < 4; mi++) {
        #pragma unroll
        for (int ni = 0; ni < 4; ni++) {
            int r0 = rowBase + wm + mi * 16 + g;
            int c0 = colBase + wn + ni * 8 + 2 * t;   // even
            if (c0 < N) {
                float bx = bias[c0], by = bias[c0 + 1];
                float v00 = acc[mi][ni][0] + bx;
                float v01 = acc[mi][ni][1] + by;
                float v10 = acc[mi][ni][2] + bx;
                float v11 = acc[mi][ni][3] + by;
                if (OM == 0) {
                    float* C = (float*)Cv;
                    float2 ra = *(const float2*)&R[(size_t)r0 * N + c0];
                    float2 rb = *(const float2*)&R[(size_t)(r0 + 8) * N + c0];
                    *(float2*)&C[(size_t)r0 * N + c0]       = make_float2(v00 + ra.x, v01 + ra.y);
                    *(float2*)&C[(size_t)(r0 + 8) * N + c0] = make_float2(v10 + rb.x, v11 + rb.y);
                } else if (OM == 4) {
                    float* C = (float*)Cv;
                    *(float2*)&C[(size_t)r0 * N + c0]       = make_float2(v00, v01);
                    *(float2*)&C[(size_t)(r0 + 8) * N + c0] = make_float2(v10, v11);
                } else {
                    if (OM == 2) {
                        v00 = fmaxf(v00, 0.f); v01 = fmaxf(v01, 0.f);
                        v10 = fmaxf(v10, 0.f); v11 = fmaxf(v11, 0.f);
                    }
                    if (OM == 3 && c0 < Hd) {
                        v00 *= 0.125f; v01 *= 0.125f;
                        v10 *= 0.125f; v11 *= 0.125f;
                    }
                    unsigned* C = (unsigned*)Cv;
                    int n2 = N >> 1;
                    C[(size_t)r0 * n2 + (c0 >> 1)]       = pack2(v00, v01);
                    C[(size_t)(r0 + 8) * n2 + (c0 >> 1)] = pack2(v10, v11);
                }
            }
        }
    }
}

// ============================================================================
// fp16 flash attention (R13: 3-buffer ring, 1 sync/tile, register P,
// direct V gather via byte_perm)
// ============================================================================
#define KPAD 36
#define VPAD 36
#define FLASH_SMEM ((3*128*KPAD + 3*128*VPAD) * 4 + 512)

__global__ void __launch_bounds__(256, 1)
flash_attn(const unsigned* __restrict__ qkv,
           const unsigned char* __restrict__ mask,
           unsigned* __restrict__ ctx)
{
    extern __shared__ unsigned fsm[];
    unsigned* Ks = fsm;                         // [3][128][KPAD]
    unsigned* Vs = Ks + 3*128*KPAD;             // [3][128][VPAD]
    unsigned char* Ms = (unsigned char*)(Vs + 3*128*VPAD);   // 3*128

    int bi = blockIdx.y;
    int b = bi >> 3, h = bi & 7;
    int qBase = blockIdx.x * 128;
    const unsigned* Qg = qkv + (size_t)b*Sd*QW2 + h*(DKd/2);
    const unsigned* Kg = qkv + (size_t)b*Sd*QW2 + HW2     + h*(DKd/2);
    const unsigned* Vg = qkv + (size_t)b*Sd*QW2 + 2*HW2   + h*(DKd/2);
    const unsigned char* mr = mask + (size_t)b*Sd;
    unsigned* Cg = ctx + (size_t)b*Sd*HW2 + h*(DKd/2);

    int tid = threadIdx.x;
    int wid = tid >> 5, lane = tid & 31;
    int g = lane >> 2, t = lane & 3;
    int wm = wid * 16;

    unsigned qf[4][4];
    {
        int r0 = qBase + wm + g, r1 = r0 + 8;
        #pragma unroll
        for (int c = 0; c < 4; c++) {
            qf[c][0] = Qg[(size_t)r0*QW2 + c*8 + t];
            qf[c][1] = Qg[(size_t)r1*QW2 + c*8 + t];
            qf[c][2] = Qg[(size_t)r0*QW2 + c*8 + 4 + t];
            qf[c][3] = Qg[(size_t)r1*QW2 + c*8 + 4 + t];
        }
    }

    float m0 = -1e30f, m1 = -1e30f, l0 = 0.f, l1 = 0.f;
    float o[8][4];
    #pragma unroll
    for (int i = 0; i < 8; i++)
        #pragma unroll
        for (int r = 0; r < 4; r++) o[i][r] = 0.f;

    auto loadTile = [&](int kt, int buf) {
        unsigned* Ktile = Ks + buf*128*KPAD;
        unsigned* Vtile = Vs + buf*128*VPAD;
        #pragma unroll
        for (int i = 0; i < 4; i++) {
            int li = tid + i * 256;
            int r = li >> 3, cq = (li & 7) * 4;
            cpa16((unsigned)__cvta_generic_to_shared(&Ktile[r*KPAD + cq]),
                  &Kg[(size_t)(kt*128 + r)*QW2 + cq]);
            cpa16((unsigned)__cvta_generic_to_shared(&Vtile[r*VPAD + cq]),
                  &Vg[(size_t)(kt*128 + r)*QW2 + cq]);
        }
        if (tid < 32) {
            uchar4 mv = *(const uchar4*)&mr[kt*128 + tid*4];
            *(uchar4*)&Ms[buf*128 + tid*4] = mv;
        }
        cp_commit();
    };

    const int NT = Sd / 128;   // 16
    loadTile(0, 0);

    for (int kt = 0; kt < NT; kt++) {
        int buf = kt % 3;
        if (kt + 1 < NT) { loadTile(kt + 1, (kt + 1) % 3); cp_wait<1>(); }
        else             { cp_wait<0>(); }
        __syncthreads();   // tile kt visible; bounds warp drift to 1 iter

        const unsigned* Ktile = Ks + buf*128*KPAD;
        const unsigned* Vtile = Vs + buf*128*VPAD;
        const unsigned char* Mt = Ms + buf*128;

        // ---- S = Q K^T ----
        float s[16][4];
        #pragma unroll
        for (int ni = 0; ni < 16; ni++)
            #pragma unroll
            for (int r = 0; r < 4; r++) s[ni][r] = 0.f;

        #pragma unroll
        for (int c = 0; c < 4; c++) {
            #pragma unroll
            for (int ni = 0; ni < 16; ni++) {
                int n = ni*8 + g;
                unsigned b0 = Ktile[n*KPAD + c*8 + t];
                unsigned b1 = Ktile[n*KPAD + c*8 + 4 + t];
                mma16(s[ni], qf[c][0], qf[c][1], qf[c][2], qf[c][3], b0, b1);
            }
        }

        // ---- mask + row max ----
        float mt0 = -1e30f, mt1 = -1e30f;
        #pragma unroll
        for (int ni = 0; ni < 16; ni++) {
            int c = ni*8 + 2*t;
            if (Mt[c])     { s[ni][0] = -1e30f; s[ni][2] = -1e30f; }
            if (Mt[c + 1]) { s[ni][1] = -1e30f; s[ni][3] = -1e30f; }
            mt0 = fmaxf(mt0, fmaxf(s[ni][0], s[ni][1]));
            mt1 = fmaxf(mt1, fmaxf(s[ni][2], s[ni][3]));
        }
        mt0 = fmaxf(mt0, __shfl_xor_sync(0xffffffffu, mt0, 1));
        mt0 = fmaxf(mt0, __shfl_xor_sync(0xffffffffu, mt0, 2));
        mt1 = fmaxf(mt1, __shfl_xor_sync(0xffffffffu, mt1, 1));
        mt1 = fmaxf(mt1, __shfl_xor_sync(0xffffffffu, mt1, 2));

        float mn0 = fmaxf(m0, mt0), mn1 = fmaxf(m1, mt1);
        float c0s = __expf(m0 - mn0), c1s = __expf(m1 - mn1);
        m0 = mn0; m1 = mn1;

        // ---- exp in-place + row sums ----
        float rs0 = 0.f, rs1 = 0.f;
        #pragma unroll
        for (int ni = 0; ni < 16; ni++) {
            s[ni][0] = __expf(s[ni][0] - m0);
            s[ni][1] = __expf(s[ni][1] - m0);
            s[ni][2] = __expf(s[ni][2] - m1);
            s[ni][3] = __expf(s[ni][3] - m1);
            rs0 += s[ni][0] + s[ni][1];
            rs1 += s[ni][2] + s[ni][3];
        }
        rs0 += __shfl_xor_sync(0xffffffffu, rs0, 1);
        rs0 += __shfl_xor_sync(0xffffffffu, rs0, 2);
        rs1 += __shfl_xor_sync(0xffffffffu, rs1, 1);
        rs1 += __shfl_xor_sync(0xffffffffu, rs1, 2);
        l0 = l0 * c0s + rs0;
        l1 = l1 * c1s + rs1;

        #pragma unroll
        for (int oni = 0; oni < 8; oni++) {
            o[oni][0] *= c0s; o[oni][1] *= c0s;
            o[oni][2] *= c1s; o[oni][3] *= c1s;
        }

        // ---- O += P V ----
        {
            unsigned sel = (g & 1) ? 0x7632u : 0x5410u;
            #pragma unroll
            for (int kk = 0; kk < 8; kk++) {
                unsigned a0 = pack2(s[2*kk][0],   s[2*kk][1]);
                unsigned a1 = pack2(s[2*kk][2],   s[2*kk][3]);
                unsigned a2 = pack2(s[2*kk+1][0], s[2*kk+1][1]);
                unsigned a3 = pack2(s[2*kk+1][2], s[2*kk+1][3]);
                const unsigned* V0a = Vtile + (2*(kk*8 + t))*VPAD;
                const unsigned* V0b = V0a + VPAD;
                const unsigned* V1a = Vtile + (2*(kk*8 + 4 + t))*VPAD;
                const unsigned* V1b = V1a + VPAD;
                #pragma unroll
                for (int oni = 0; oni < 8; oni++) {
                    int dw = oni*4 + (g >> 1);
                    unsigned b0 = __byte_perm(V0a[dw], V0b[dw], sel);
                    unsigned b1 = __byte_perm(V1a[dw], V1b[dw], sel);
                    mma16(o[oni], a0, a1, a2, a3, b0, b1);
                }
            }
        }
    }

    // ---- epilogue ----
    float i0 = 1.f / l0, i1 = 1.f / l1;
    int r0 = qBase + wm + g, r1 = r0 + 8;
    #pragma unroll
    for (int oni = 0; oni < 8; oni++) {
        int wrd = oni*4 + t;
        Cg[(size_t)r0*HW2 + wrd] = pack2(o[oni][0] * i0, o[oni][1] * i0);
        Cg[(size_t)r1*HW2 + wrd] = pack2(o[oni][2] * i1, o[oni][3] * i1);
    }
}

// ---------------- launch ----------------
extern "C" void kernel_launch(void* const* d_in, const int* in_sizes, int n_in,
                              void* d_out, int out_size)
{
    const int*           src  = (const int*)d_in[0];
    const unsigned char* mask = (const unsigned char*)d_in[1];
    const float* emb  = (const float*)d_in[2];
    const float* Wq   = (const float*)d_in[3];
    const float* bq   = (const float*)d_in[4];
    const float* Wk   = (const float*)d_in[5];
    const float* bk   = (const float*)d_in[6];
    const float* Wv   = (const float*)d_in[7];
    const float* bv   = (const float*)d_in[8];
    const float* Wo   = (const float*)d_in[9];
    const float* bo   = (const float*)d_in[10];
    const float* ln1g = (const float*)d_in[11];
    const float* ln1b = (const float*)d_in[12];
    const float* W1   = (const float*)d_in[13];
    const float* b1   = (const float*)d_in[14];
    const float* W2   = (const float*)d_in[15];
    const float* b2   = (const float*)d_in[16];
    const float* ln2g = (const float*)d_in[17];
    const float* ln2b = (const float*)d_in[18];
    const float* lnfg = (const float*)d_in[19];
    const float* lnfb = (const float*)d_in[20];
    const float* Wg   = (const float*)d_in[21];
    const float* bg   = (const float*)d_in[22];
    float* out = (float*)d_out;

    float *x;   unsigned *h, *qkv, *ctx, *ff;
    unsigned *wqkv, *wo, *w1, *w2, *wg;  float *bqkv;
    cudaGetSymbolAddress((void**)&x,    g_x);
    cudaGetSymbolAddress((void**)&h,    g_h);
    cudaGetSymbolAddress((void**)&qkv,  g_qkv);
    cudaGetSymbolAddress((void**)&ctx,  g_ctx);
    cudaGetSymbolAddress((void**)&ff,   g_ff);
    cudaGetSymbolAddress((void**)&wqkv, g_wqkv);
    cudaGetSymbolAddress((void**)&wo,   g_wo);
    cudaGetSymbolAddress((void**)&w1,   g_w1);
    cudaGetSymbolAddress((void**)&w2,   g_w2);
    cudaGetSymbolAddress((void**)&wg,   g_wg);
    cudaGetSymbolAddress((void**)&bqkv, g_bqkv);

    static bool attr_set = false;
    if (!attr_set) {
        cudaFuncSetAttribute(flash_attn,
                             cudaFuncAttributeMaxDynamicSharedMemorySize, FLASH_SMEM);
        cudaFuncSetAttribute(gemm_hk<0>,
                             cudaFuncAttributeMaxDynamicSharedMemorySize, GEMM_SMEM);
        cudaFuncSetAttribute(gemm_hk<2>,
                             cudaFuncAttributeMaxDynamicSharedMemorySize, GEMM_SMEM);
        cudaFuncSetAttribute(gemm_hk<3>,
                             cudaFuncAttributeMaxDynamicSharedMemorySize, GEMM_SMEM);
        cudaFuncSetAttribute(gemm_hk<4>,
                             cudaFuncAttributeMaxDynamicSharedMemorySize, GEMM_SMEM);
        attr_set = true;
    }

    // ---- prepack weights to half2 words (2 launches total) ----
    pack_qkv_kernel<<<1184, 256>>>(Wq, Wk, Wv, wqkv);
    pack_bqkv_kernel<<<(Lx*QKVW + 255)/256, 256>>>(bq, bk, bv, bqkv);
    conv_pack_all<<<1184, 256>>>(Wo, wo, W1, w1, W2, w2, Wg, wg);

    embed_kernel<<<(Nt*Hd + 255)/256, 256>>>(src, emb, x);

    dim3 gQKV(QKVW/128, Nt/128);
    dim3 gH(Hd/128,  Nt/128);
    dim3 gF(FFd/128, Nt/128);
    dim3 gV((Vocab+127)/128, Nt/128);

    for (int l = 0; l < Lx; l++) {
        layernorm_kernel<<<Nt/8, 256>>>(x, ln1g + (size_t)l*Hd, ln1b + (size_t)l*Hd, h);

        // fused QKV (q cols pre-scaled by 1/8, half2 out)
        gemm_hk<3><<<gQKV, 256, GEMM_SMEM>>>(h, wqkv + (size_t)l*HW2*QKVW, bqkv + (size_t)l*QKVW,
                                             nullptr, qkv, Nt, QKVW, HW2);

        flash_attn<<<dim3(Sd/128, Bd*NHd), 256, FLASH_SMEM>>>(qkv, mask, ctx);

        // x = x + ctx @ Wo + bo
        gemm_hk<0><<<gH, 256, GEMM_SMEM>>>(ctx, wo + (size_t)l*HW2*Hd, bo + (size_t)l*Hd,
                                           x, x, Nt, Hd, HW2);

        layernorm_kernel<<<Nt/8, 256>>>(x, ln2g + (size_t)l*Hd, ln2b + (size_t)l*Hd, h);

        // ff = relu(h @ W1 + b1) (half2 out)
        gemm_hk<2><<<gF, 256, GEMM_SMEM>>>(h, w1 + (size_t)l*HW2*FFd, b1 + (size_t)l*FFd,
                                           nullptr, ff, Nt, FFd, HW2);
        // x = x + ff @ W2 + b2
        gemm_hk<0><<<gH, 256, GEMM_SMEM>>>(ff, w2 + (size_t)l*FW2*Hd, b2 + (size_t)l*Hd,
                                           x, x, Nt, Hd, FW2);
    }

    layernorm_kernel<<<Nt/8, 256>>>(x, lnfg, lnfb, h);
    gemm_hk<4><<<gV, 256, GEMM_SMEM>>>(h, wg, bg, nullptr, out, Nt, Vocab, HW2);
}